// round 1
// baseline (speedup 1.0000x reference)
#include <cuda_runtime.h>
#include <math.h>

#define B_ 2
#define T_ 2048
#define C_ 2048
#define H_ 16
#define D_ 128
#define M_ (B_*T_)            /* 4096 */
#define N1_ (3*C_)            /* 6144 */
#define NKV (B_*H_*T_*D_)     /* 8388608 */

// Scratch (allocation-free): q,k,v in [B,H,T,D], attn output in [B,T,C]
__device__ float g_q[NKV];
__device__ float g_k[NKV];
__device__ float g_v[NKV];
__device__ float g_attn[M_*C_];

// ---------------------------------------------------------------------------
// GEMM 1: qkv = x @ W_qkv + b_qkv, scattered into per-head q/k/v layouts.
// Classic SIMT SGEMM: 128x128 block tile, BK=8, 256 threads, 8x8 per thread.
// ---------------------------------------------------------------------------
__global__ void __launch_bounds__(256) qkv_gemm_kernel(
    const float* __restrict__ A,      // x [4096, 2048]
    const float* __restrict__ W,      // W_qkv [2048, 6144]
    const float* __restrict__ bias)   // [6144]
{
    __shared__ float As[8][128];
    __shared__ float Bs[8][128];
    const int bm = blockIdx.y << 7;
    const int bn = blockIdx.x << 7;
    const int tid = threadIdx.x;
    const int a_row = tid >> 1;
    const int a_k   = (tid & 1) << 2;
    const int b_k   = tid >> 5;
    const int b_col = (tid & 31) << 2;
    const int ty = tid >> 4, tx = tid & 15;
    const int tm = ty << 3, tn = tx << 3;

    float acc[8][8];
    #pragma unroll
    for (int i = 0; i < 8; i++)
        #pragma unroll
        for (int j = 0; j < 8; j++) acc[i][j] = 0.f;

    for (int k0 = 0; k0 < 2048; k0 += 8) {
        float4 av = *(const float4*)(A + (bm + a_row) * 2048 + k0 + a_k);
        As[a_k + 0][a_row] = av.x;
        As[a_k + 1][a_row] = av.y;
        As[a_k + 2][a_row] = av.z;
        As[a_k + 3][a_row] = av.w;
        *(float4*)&Bs[b_k][b_col] =
            *(const float4*)(W + (k0 + b_k) * 6144 + bn + b_col);
        __syncthreads();
        #pragma unroll
        for (int kk = 0; kk < 8; kk++) {
            float a[8], b[8];
            *(float4*)&a[0] = *(const float4*)&As[kk][tm];
            *(float4*)&a[4] = *(const float4*)&As[kk][tm + 4];
            *(float4*)&b[0] = *(const float4*)&Bs[kk][tn];
            *(float4*)&b[4] = *(const float4*)&Bs[kk][tn + 4];
            #pragma unroll
            for (int i = 0; i < 8; i++)
                #pragma unroll
                for (int j = 0; j < 8; j++)
                    acc[i][j] += a[i] * b[j];
        }
        __syncthreads();
    }

    // Epilogue: add bias, scatter to [B,H,T,D] q/k/v
    #pragma unroll
    for (int i = 0; i < 8; i++) {
        const int m = bm + tm + i;
        const int bi = m >> 11;        // /2048 -> batch
        const int t  = m & 2047;
        #pragma unroll
        for (int j = 0; j < 8; j++) {
            const int n = bn + tn + j;
            const float v = acc[i][j] + bias[n];
            const int which = n >> 11;      // 0:q 1:k 2:v
            const int cc = n & 2047;
            const int h = cc >> 7;
            const int d = cc & 127;
            float* dst = (which == 0) ? g_q : ((which == 1) ? g_k : g_v);
            dst[((bi * H_ + h) * T_ + t) * D_ + d] = v;
        }
    }
}

// ---------------------------------------------------------------------------
// GEMM 2 (out proj): out = attn @ W_out + b_out
// ---------------------------------------------------------------------------
__global__ void __launch_bounds__(256) out_gemm_kernel(
    const float* __restrict__ W,      // W_out [2048, 2048]
    const float* __restrict__ bias,   // [2048]
    float* __restrict__ Cout)         // [4096, 2048]
{
    __shared__ float As[8][128];
    __shared__ float Bs[8][128];
    const int bm = blockIdx.y << 7;
    const int bn = blockIdx.x << 7;
    const int tid = threadIdx.x;
    const int a_row = tid >> 1;
    const int a_k   = (tid & 1) << 2;
    const int b_k   = tid >> 5;
    const int b_col = (tid & 31) << 2;
    const int ty = tid >> 4, tx = tid & 15;
    const int tm = ty << 3, tn = tx << 3;
    const float* A = g_attn;

    float acc[8][8];
    #pragma unroll
    for (int i = 0; i < 8; i++)
        #pragma unroll
        for (int j = 0; j < 8; j++) acc[i][j] = 0.f;

    for (int k0 = 0; k0 < 2048; k0 += 8) {
        float4 av = *(const float4*)(A + (bm + a_row) * 2048 + k0 + a_k);
        As[a_k + 0][a_row] = av.x;
        As[a_k + 1][a_row] = av.y;
        As[a_k + 2][a_row] = av.z;
        As[a_k + 3][a_row] = av.w;
        *(float4*)&Bs[b_k][b_col] =
            *(const float4*)(W + (k0 + b_k) * 2048 + bn + b_col);
        __syncthreads();
        #pragma unroll
        for (int kk = 0; kk < 8; kk++) {
            float a[8], b[8];
            *(float4*)&a[0] = *(const float4*)&As[kk][tm];
            *(float4*)&a[4] = *(const float4*)&As[kk][tm + 4];
            *(float4*)&b[0] = *(const float4*)&Bs[kk][tn];
            *(float4*)&b[4] = *(const float4*)&Bs[kk][tn + 4];
            #pragma unroll
            for (int i = 0; i < 8; i++)
                #pragma unroll
                for (int j = 0; j < 8; j++)
                    acc[i][j] += a[i] * b[j];
        }
        __syncthreads();
    }

    #pragma unroll
    for (int i = 0; i < 8; i++) {
        const int m = bm + tm + i;
        #pragma unroll
        for (int j = 0; j < 8; j += 4) {
            const int n = bn + tn + j;
            float4 o;
            o.x = acc[i][j + 0] + bias[n + 0];
            o.y = acc[i][j + 1] + bias[n + 1];
            o.z = acc[i][j + 2] + bias[n + 2];
            o.w = acc[i][j + 3] + bias[n + 3];
            *(float4*)(Cout + m * 2048 + n) = o;
        }
    }
}

// ---------------------------------------------------------------------------
// Flash attention: causal, Br=Bc=64, D=128, 256 threads.
// Qs/Ks stored [d][i] transposed; Vs [j][d]; Ps [j][i] padded stride 65.
// Thread (ty,tx) 16x16 grid: S micro-tile 4x4 (rows ty*4.., cols tx*4..),
// O micro-tile 4x8 (rows ty*4.., cols tx*8..). Each row is owned by one
// 16-lane half-warp -> softmax reductions are pure shfl_xor.
// ---------------------------------------------------------------------------
__global__ void __launch_bounds__(256) attn_kernel()
{
    extern __shared__ float sm[];
    float* Qs = sm;                 // [128][64]
    float* Ks = sm + 8192;          // [128][64]
    float* Vs = sm + 16384;         // [64][128]
    float* Ps = sm + 24576;         // [64][65]

    const int it  = blockIdx.x;     // q tile 0..31
    const int bh  = blockIdx.y;     // 0..31 = b*16+h
    const int tid = threadIdx.x;
    const int ty = tid >> 4, tx = tid & 15;

    const float* Qg = g_q + (size_t)bh * (T_ * D_);
    const float* Kg = g_k + (size_t)bh * (T_ * D_);
    const float* Vg = g_v + (size_t)bh * (T_ * D_);

    // Load Q tile transposed: Qs[d][i]
    for (int idx = tid; idx < 2048; idx += 256) {
        const int row = idx >> 5;          // 0..63
        const int c4  = (idx & 31) << 2;   // 0..124
        float4 v = *(const float4*)(Qg + (it * 64 + row) * 128 + c4);
        Qs[(c4 + 0) * 64 + row] = v.x;
        Qs[(c4 + 1) * 64 + row] = v.y;
        Qs[(c4 + 2) * 64 + row] = v.z;
        Qs[(c4 + 3) * 64 + row] = v.w;
    }

    float m_r[4], l_r[4], O[4][8];
    #pragma unroll
    for (int r = 0; r < 4; r++) {
        m_r[r] = -INFINITY;
        l_r[r] = 0.f;
        #pragma unroll
        for (int c = 0; c < 8; c++) O[r][c] = 0.f;
    }
    const float scale = 0.08838834764831845f;  // 1/sqrt(128)

    for (int jt = 0; jt <= it; jt++) {
        __syncthreads();  // Ks/Vs/Ps safe to overwrite (also covers Q load)
        for (int idx = tid; idx < 2048; idx += 256) {
            const int row = idx >> 5;
            const int c4  = (idx & 31) << 2;
            float4 v = *(const float4*)(Kg + (jt * 64 + row) * 128 + c4);
            Ks[(c4 + 0) * 64 + row] = v.x;
            Ks[(c4 + 1) * 64 + row] = v.y;
            Ks[(c4 + 2) * 64 + row] = v.z;
            Ks[(c4 + 3) * 64 + row] = v.w;
            *(float4*)&Vs[idx << 2] =
                *(const float4*)(Vg + jt * 64 * 128 + (idx << 2));
        }
        __syncthreads();

        // S = Q K^T (4x4 per thread)
        float s[4][4];
        #pragma unroll
        for (int r = 0; r < 4; r++)
            #pragma unroll
            for (int c = 0; c < 4; c++) s[r][c] = 0.f;

        #pragma unroll 8
        for (int d = 0; d < 128; d++) {
            float4 a4 = *(const float4*)&Qs[d * 64 + (ty << 2)];
            float4 b4 = *(const float4*)&Ks[d * 64 + (tx << 2)];
            float a[4] = {a4.x, a4.y, a4.z, a4.w};
            float b[4] = {b4.x, b4.y, b4.z, b4.w};
            #pragma unroll
            for (int r = 0; r < 4; r++)
                #pragma unroll
                for (int c = 0; c < 4; c++)
                    s[r][c] += a[r] * b[c];
        }

        // scale + causal mask (only diagonal tile needs masking)
        if (jt == it) {
            #pragma unroll
            for (int r = 0; r < 4; r++)
                #pragma unroll
                for (int c = 0; c < 4; c++)
                    s[r][c] = ((tx << 2) + c > (ty << 2) + r)
                                  ? -INFINITY : s[r][c] * scale;
        } else {
            #pragma unroll
            for (int r = 0; r < 4; r++)
                #pragma unroll
                for (int c = 0; c < 4; c++) s[r][c] *= scale;
        }

        // Online softmax per row (16-lane shfl reductions)
        #pragma unroll
        for (int r = 0; r < 4; r++) {
            float rm = fmaxf(fmaxf(s[r][0], s[r][1]), fmaxf(s[r][2], s[r][3]));
            #pragma unroll
            for (int o = 8; o; o >>= 1)
                rm = fmaxf(rm, __shfl_xor_sync(0xffffffffu, rm, o));
            const float mn = fmaxf(m_r[r], rm);
            const float alpha = __expf(m_r[r] - mn);
            float rs = 0.f;
            #pragma unroll
            for (int c = 0; c < 4; c++) {
                const float p = __expf(s[r][c] - mn);
                s[r][c] = p;
                rs += p;
            }
            #pragma unroll
            for (int o = 8; o; o >>= 1)
                rs += __shfl_xor_sync(0xffffffffu, rs, o);
            l_r[r] = l_r[r] * alpha + rs;
            m_r[r] = mn;
            #pragma unroll
            for (int c = 0; c < 8; c++) O[r][c] *= alpha;
            #pragma unroll
            for (int c = 0; c < 4; c++)
                Ps[((tx << 2) + c) * 65 + (ty << 2) + r] = s[r][c];
        }
        __syncthreads();

        // O += P @ V (4x8 per thread)
        #pragma unroll 4
        for (int j = 0; j < 64; j++) {
            float a[4];
            a[0] = Ps[j * 65 + (ty << 2) + 0];
            a[1] = Ps[j * 65 + (ty << 2) + 1];
            a[2] = Ps[j * 65 + (ty << 2) + 2];
            a[3] = Ps[j * 65 + (ty << 2) + 3];
            float4 b0 = *(const float4*)&Vs[j * 128 + (tx << 3)];
            float4 b1 = *(const float4*)&Vs[j * 128 + (tx << 3) + 4];
            float b[8] = {b0.x, b0.y, b0.z, b0.w, b1.x, b1.y, b1.z, b1.w};
            #pragma unroll
            for (int r = 0; r < 4; r++)
                #pragma unroll
                for (int c = 0; c < 8; c++)
                    O[r][c] += a[r] * b[c];
        }
    }

    // Normalize and write to [B,T,C] layout for the output projection
    const int bi = bh >> 4, h = bh & 15;
    #pragma unroll
    for (int r = 0; r < 4; r++) {
        const float inv = 1.0f / l_r[r];
        const int qi = it * 64 + (ty << 2) + r;
        float* dst = g_attn + ((size_t)bi * T_ + qi) * C_ + h * D_ + (tx << 3);
        float4 o0 = make_float4(O[r][0] * inv, O[r][1] * inv,
                                O[r][2] * inv, O[r][3] * inv);
        float4 o1 = make_float4(O[r][4] * inv, O[r][5] * inv,
                                O[r][6] * inv, O[r][7] * inv);
        *(float4*)dst       = o0;
        *(float4*)(dst + 4) = o1;
    }
}

// ---------------------------------------------------------------------------
// Launch
// ---------------------------------------------------------------------------
extern "C" void kernel_launch(void* const* d_in, const int* in_sizes, int n_in,
                              void* d_out, int out_size)
{
    // Identify inputs by element count (robust to metadata ordering of the
    // two 4194304-element tensors: mask comes before W_out).
    const float* x = nullptr;
    const float* W_qkv = nullptr;
    const float* b_qkv = nullptr;
    const float* W_out = nullptr;
    const float* b_out = nullptr;
    int n4m_seen = 0;
    for (int i = 0; i < n_in; i++) {
        const int sz = in_sizes[i];
        if (sz == M_ * C_ && x == nullptr) x = (const float*)d_in[i];           // 8388608
        else if (sz == C_ * N1_) W_qkv = (const float*)d_in[i];                 // 12582912
        else if (sz == N1_) b_qkv = (const float*)d_in[i];                      // 6144
        else if (sz == C_ * C_) {                                               // 4194304: mask then W_out
            if (n4m_seen == 0) { /* mask - ignored, causal is hardcoded */ }
            else W_out = (const float*)d_in[i];
            n4m_seen++;
        }
        else if (sz == C_) b_out = (const float*)d_in[i];                       // 2048
    }
    float* out = (float*)d_out;

    cudaFuncSetAttribute(attn_kernel,
                         cudaFuncAttributeMaxDynamicSharedMemorySize, 114944);

    qkv_gemm_kernel<<<dim3(48, 32), 256>>>(x, W_qkv, b_qkv);
    attn_kernel<<<dim3(32, 32), 256, 114944>>>();
    out_gemm_kernel<<<dim3(16, 32), 256>>>(W_out, b_out, out);

    // Reference returns (out, (k, v)) — append k,v if the output buffer has room.
    const size_t nbytes = (size_t)NKV * sizeof(float);
    if (out_size >= 2 * NKV)
        cudaMemcpyFromSymbolAsync(out + NKV, g_k, nbytes, 0,
                                  cudaMemcpyDeviceToDevice, 0);
    if (out_size >= 3 * NKV)
        cudaMemcpyFromSymbolAsync(out + 2 * NKV, g_v, nbytes, 0,
                                  cudaMemcpyDeviceToDevice, 0);
}

// round 3
// speedup vs baseline: 1.8131x; 1.8131x over previous
#include <cuda_runtime.h>
#include <math.h>
#include <stdint.h>

#define B_ 2
#define T_ 2048
#define C_ 2048
#define H_ 16
#define D_ 128
#define M_ (B_*T_)            /* 4096 */
#define N1_ (3*C_)            /* 6144 */
#define NKV (B_*H_*T_*D_)     /* 8388608 */

// Scratch (allocation-free)
__device__ float g_q[NKV];
__device__ float g_k[NKV];
__device__ float g_v[NKV];
__device__ float g_attn[M_*C_];

// ---------------------------------------------------------------------------
// Helpers (family-portable only: cp.async + mma.sync — NO tcgen05 on this
// toolchain, PTX is compiled for compute_103 without the 'a' feature set)
// ---------------------------------------------------------------------------
__device__ __forceinline__ uint32_t smem_u32(const void* p) {
    uint32_t a;
    asm("{ .reg .u64 t; cvta.to.shared.u64 t, %1; cvt.u32.u64 %0, t; }"
        : "=r"(a) : "l"(p));
    return a;
}
__device__ __forceinline__ void cpasync16(uint32_t dst, const void* src) {
    asm volatile("cp.async.cg.shared.global [%0], [%1], 16;"
                 :: "r"(dst), "l"(src) : "memory");
}
__device__ __forceinline__ uint32_t f2tf(float x) {
    uint32_t u;
    asm("cvt.rna.tf32.f32 %0, %1;" : "=r"(u) : "f"(x));
    return u;
}
__device__ __forceinline__ void mma_tf32(float* d, const uint32_t* a,
                                         const uint32_t* b) {
    asm volatile(
        "mma.sync.aligned.m16n8k8.row.col.f32.tf32.tf32.f32 "
        "{%0,%1,%2,%3}, {%4,%5,%6,%7}, {%8,%9}, {%0,%1,%2,%3};"
        : "+f"(d[0]), "+f"(d[1]), "+f"(d[2]), "+f"(d[3])
        : "r"(a[0]), "r"(a[1]), "r"(a[2]), "r"(a[3]), "r"(b[0]), "r"(b[1]));
}

// ---------------------------------------------------------------------------
// tf32 mma.sync GEMM: C[4096, N] = A[4096,2048] @ W[2048,N] + bias
// CTA 128x128, BK=16, 256 threads (8 warps, 4(m) x 2(n), warp tile 32x64).
// Double-buffered cp.async. MODE 0: scatter into g_q/g_k/g_v; MODE 1: store.
// Smem padding chosen for conflict-free fragment LDS:
//   As[m][k] stride 20  -> bank (20u+p)%32 is a permutation
//   Bs[k][n] stride 136 -> bank (8p+u)%32  is a permutation
// ---------------------------------------------------------------------------
template <int MODE>
__global__ void __launch_bounds__(256) tc_gemm_kernel(
    const float* __restrict__ Ag, const float* __restrict__ Wg,
    const float* __restrict__ bias, float* __restrict__ Cout, int ldW)
{
    __shared__ float As[2][128][20];
    __shared__ float Bs[2][16][136];

    const int tid  = threadIdx.x;
    const int warp = tid >> 5;
    const int lane = tid & 31;
    const int wm = warp & 3;          // m block of 32
    const int wn = warp >> 2;         // n block of 64
    const int bm = blockIdx.y << 7;
    const int bn = blockIdx.x << 7;
    const int lp = lane & 3;          // thread-in-group (k)
    const int lg = lane >> 2;         // group id

    float acc[2][8][4];
    #pragma unroll
    for (int mt = 0; mt < 2; mt++)
        #pragma unroll
        for (int nt = 0; nt < 8; nt++)
            #pragma unroll
            for (int i = 0; i < 4; i++) acc[mt][nt][i] = 0.f;

    auto load_tiles = [&](int it, int s) {
        #pragma unroll
        for (int i = 0; i < 2; i++) {
            const int lin = tid + 256 * i;
            const int am = lin >> 2, ak = (lin & 3) << 2;
            cpasync16(smem_u32(&As[s][am][ak]),
                      Ag + (size_t)(bm + am) * 2048 + it * 16 + ak);
            const int bk = lin >> 5, bn4 = (lin & 31) << 2;
            cpasync16(smem_u32(&Bs[s][bk][bn4]),
                      Wg + (size_t)(it * 16 + bk) * ldW + bn + bn4);
        }
        asm volatile("cp.async.commit_group;" ::: "memory");
    };

    const int NIT = 2048 / 16;  // 128
    load_tiles(0, 0);
    load_tiles(1, 1);

    for (int it = 0; it < NIT; it++) {
        const int cur = it & 1;
        if (it == NIT - 1) asm volatile("cp.async.wait_group 0;" ::: "memory");
        else               asm volatile("cp.async.wait_group 1;" ::: "memory");
        __syncthreads();

        #pragma unroll
        for (int ks = 0; ks < 2; ks++) {
            const int c = ks * 8;
            uint32_t af[2][4];
            #pragma unroll
            for (int mt = 0; mt < 2; mt++) {
                const int r0 = wm * 32 + mt * 16 + lg;
                af[mt][0] = f2tf(As[cur][r0    ][c + lp]);
                af[mt][1] = f2tf(As[cur][r0 + 8][c + lp]);
                af[mt][2] = f2tf(As[cur][r0    ][c + 4 + lp]);
                af[mt][3] = f2tf(As[cur][r0 + 8][c + 4 + lp]);
            }
            #pragma unroll
            for (int nt = 0; nt < 8; nt++) {
                const int nc = wn * 64 + nt * 8 + lg;
                uint32_t bf[2];
                bf[0] = f2tf(Bs[cur][c + lp    ][nc]);
                bf[1] = f2tf(Bs[cur][c + 4 + lp][nc]);
                mma_tf32(acc[0][nt], af[0], bf);
                mma_tf32(acc[1][nt], af[1], bf);
            }
        }
        __syncthreads();
        if (it + 2 < NIT) load_tiles(it + 2, cur);
    }

    // Epilogue: bias + store (float2 per c-pair)
    #pragma unroll
    for (int mt = 0; mt < 2; mt++) {
        #pragma unroll
        for (int half = 0; half < 2; half++) {
            const int m = bm + wm * 32 + mt * 16 + lg + half * 8;
            #pragma unroll
            for (int nt = 0; nt < 8; nt++) {
                const int d = wn * 64 + nt * 8 + lp * 2;   // col within 128
                const float c0 = acc[mt][nt][half * 2 + 0];
                const float c1 = acc[mt][nt][half * 2 + 1];
                float2 bv = *(const float2*)(bias + bn + d);
                float2 o = make_float2(c0 + bv.x, c1 + bv.y);
                if (MODE == 0) {
                    const int which = bn >> 11;
                    const int h = (bn & 2047) >> 7;
                    const int bi = m >> 11, t = m & 2047;
                    float* base = (which == 0) ? g_q
                                 : ((which == 1) ? g_k : g_v);
                    *(float2*)(base + (((size_t)bi * H_ + h) * T_ + t) * D_ + d) = o;
                } else {
                    *(float2*)(Cout + (size_t)m * 2048 + bn + d) = o;
                }
            }
        }
    }
}

// ---------------------------------------------------------------------------
// Flash attention (SIMT, unchanged from round 1): causal, Br=Bc=64, D=128.
// ---------------------------------------------------------------------------
__global__ void __launch_bounds__(256) attn_kernel()
{
    extern __shared__ char dynsm[];
    float* sm = (float*)dynsm;
    float* Qs = sm;                 // [128][64]
    float* Ks = sm + 8192;          // [128][64]
    float* Vs = sm + 16384;         // [64][128]
    float* Ps = sm + 24576;         // [64][65]

    const int it  = blockIdx.x;
    const int bh  = blockIdx.y;
    const int tid = threadIdx.x;
    const int ty = tid >> 4, tx = tid & 15;

    const float* Qg = g_q + (size_t)bh * (T_ * D_);
    const float* Kg = g_k + (size_t)bh * (T_ * D_);
    const float* Vg = g_v + (size_t)bh * (T_ * D_);

    for (int idx = tid; idx < 2048; idx += 256) {
        const int row = idx >> 5;
        const int c4  = (idx & 31) << 2;
        float4 v = *(const float4*)(Qg + (it * 64 + row) * 128 + c4);
        Qs[(c4 + 0) * 64 + row] = v.x;
        Qs[(c4 + 1) * 64 + row] = v.y;
        Qs[(c4 + 2) * 64 + row] = v.z;
        Qs[(c4 + 3) * 64 + row] = v.w;
    }

    float m_r[4], l_r[4], O[4][8];
    #pragma unroll
    for (int r = 0; r < 4; r++) {
        m_r[r] = -INFINITY; l_r[r] = 0.f;
        #pragma unroll
        for (int c = 0; c < 8; c++) O[r][c] = 0.f;
    }
    const float scale = 0.08838834764831845f;

    for (int jt = 0; jt <= it; jt++) {
        __syncthreads();
        for (int idx = tid; idx < 2048; idx += 256) {
            const int row = idx >> 5;
            const int c4  = (idx & 31) << 2;
            float4 v = *(const float4*)(Kg + (jt * 64 + row) * 128 + c4);
            Ks[(c4 + 0) * 64 + row] = v.x;
            Ks[(c4 + 1) * 64 + row] = v.y;
            Ks[(c4 + 2) * 64 + row] = v.z;
            Ks[(c4 + 3) * 64 + row] = v.w;
            *(float4*)&Vs[idx << 2] =
                *(const float4*)(Vg + jt * 64 * 128 + (idx << 2));
        }
        __syncthreads();

        float s[4][4];
        #pragma unroll
        for (int r = 0; r < 4; r++)
            #pragma unroll
            for (int c = 0; c < 4; c++) s[r][c] = 0.f;

        #pragma unroll 8
        for (int d = 0; d < 128; d++) {
            float4 a4 = *(const float4*)&Qs[d * 64 + (ty << 2)];
            float4 b4 = *(const float4*)&Ks[d * 64 + (tx << 2)];
            float a[4] = {a4.x, a4.y, a4.z, a4.w};
            float b[4] = {b4.x, b4.y, b4.z, b4.w};
            #pragma unroll
            for (int r = 0; r < 4; r++)
                #pragma unroll
                for (int c = 0; c < 4; c++)
                    s[r][c] += a[r] * b[c];
        }

        if (jt == it) {
            #pragma unroll
            for (int r = 0; r < 4; r++)
                #pragma unroll
                for (int c = 0; c < 4; c++)
                    s[r][c] = ((tx << 2) + c > (ty << 2) + r)
                                  ? -INFINITY : s[r][c] * scale;
        } else {
            #pragma unroll
            for (int r = 0; r < 4; r++)
                #pragma unroll
                for (int c = 0; c < 4; c++) s[r][c] *= scale;
        }

        #pragma unroll
        for (int r = 0; r < 4; r++) {
            float rm = fmaxf(fmaxf(s[r][0], s[r][1]), fmaxf(s[r][2], s[r][3]));
            #pragma unroll
            for (int o = 8; o; o >>= 1)
                rm = fmaxf(rm, __shfl_xor_sync(0xffffffffu, rm, o));
            const float mn = fmaxf(m_r[r], rm);
            const float alpha = __expf(m_r[r] - mn);
            float rs = 0.f;
            #pragma unroll
            for (int c = 0; c < 4; c++) {
                const float p = __expf(s[r][c] - mn);
                s[r][c] = p; rs += p;
            }
            #pragma unroll
            for (int o = 8; o; o >>= 1)
                rs += __shfl_xor_sync(0xffffffffu, rs, o);
            l_r[r] = l_r[r] * alpha + rs;
            m_r[r] = mn;
            #pragma unroll
            for (int c = 0; c < 8; c++) O[r][c] *= alpha;
            #pragma unroll
            for (int c = 0; c < 4; c++)
                Ps[((tx << 2) + c) * 65 + (ty << 2) + r] = s[r][c];
        }
        __syncthreads();

        #pragma unroll 4
        for (int j = 0; j < 64; j++) {
            float a[4];
            a[0] = Ps[j * 65 + (ty << 2) + 0];
            a[1] = Ps[j * 65 + (ty << 2) + 1];
            a[2] = Ps[j * 65 + (ty << 2) + 2];
            a[3] = Ps[j * 65 + (ty << 2) + 3];
            float4 b0 = *(const float4*)&Vs[j * 128 + (tx << 3)];
            float4 b1 = *(const float4*)&Vs[j * 128 + (tx << 3) + 4];
            float b[8] = {b0.x, b0.y, b0.z, b0.w, b1.x, b1.y, b1.z, b1.w};
            #pragma unroll
            for (int r = 0; r < 4; r++)
                #pragma unroll
                for (int c = 0; c < 8; c++)
                    O[r][c] += a[r] * b[c];
        }
    }

    const int bi = bh >> 4, h = bh & 15;
    #pragma unroll
    for (int r = 0; r < 4; r++) {
        const float inv = 1.0f / l_r[r];
        const int qi = it * 64 + (ty << 2) + r;
        float* dst = g_attn + ((size_t)bi * T_ + qi) * C_ + h * D_ + (tx << 3);
        float4 o0 = make_float4(O[r][0] * inv, O[r][1] * inv,
                                O[r][2] * inv, O[r][3] * inv);
        float4 o1 = make_float4(O[r][4] * inv, O[r][5] * inv,
                                O[r][6] * inv, O[r][7] * inv);
        *(float4*)dst       = o0;
        *(float4*)(dst + 4) = o1;
    }
}

// ---------------------------------------------------------------------------
// Launch
// ---------------------------------------------------------------------------
extern "C" void kernel_launch(void* const* d_in, const int* in_sizes, int n_in,
                              void* d_out, int out_size)
{
    const float* x = nullptr;
    const float* W_qkv = nullptr;
    const float* b_qkv = nullptr;
    const float* W_out = nullptr;
    const float* b_out = nullptr;
    int n4m_seen = 0;
    for (int i = 0; i < n_in; i++) {
        const int sz = in_sizes[i];
        if (sz == M_ * C_ && x == nullptr) x = (const float*)d_in[i];
        else if (sz == C_ * N1_) W_qkv = (const float*)d_in[i];
        else if (sz == N1_) b_qkv = (const float*)d_in[i];
        else if (sz == C_ * C_) {
            if (n4m_seen == 1) W_out = (const float*)d_in[i];
            n4m_seen++;
        }
        else if (sz == C_) b_out = (const float*)d_in[i];
    }
    float* out = (float*)d_out;

    void* attn_ptr = nullptr;
    cudaGetSymbolAddress(&attn_ptr, g_attn);

    cudaFuncSetAttribute(attn_kernel,
                         cudaFuncAttributeMaxDynamicSharedMemorySize, 114944);

    // qkv: N=6144 -> 48 x 32 CTAs
    tc_gemm_kernel<0><<<dim3(48, 32), 256>>>(x, W_qkv, b_qkv, nullptr, 6144);
    attn_kernel<<<dim3(32, 32), 256, 114944>>>();
    // out proj: N=2048 -> 16 x 32 CTAs
    tc_gemm_kernel<1><<<dim3(16, 32), 256>>>((const float*)attn_ptr,
                                             W_out, b_out, out, 2048);

    const size_t nbytes = (size_t)NKV * sizeof(float);
    if (out_size >= 2 * NKV)
        cudaMemcpyFromSymbolAsync(out + NKV, g_k, nbytes, 0,
                                  cudaMemcpyDeviceToDevice, 0);
    if (out_size >= 3 * NKV)
        cudaMemcpyFromSymbolAsync(out + 2 * NKV, g_v, nbytes, 0,
                                  cudaMemcpyDeviceToDevice, 0);
}

// round 4
// speedup vs baseline: 3.3126x; 1.8270x over previous
#include <cuda_runtime.h>
#include <math.h>
#include <stdint.h>

#define B_ 2
#define T_ 2048
#define C_ 2048
#define H_ 16
#define D_ 128
#define M_ (B_*T_)            /* 4096 */
#define N1_ (3*C_)            /* 6144 */
#define NKV (B_*H_*T_*D_)     /* 8388608 */

// Scratch (allocation-free)
__device__ float g_q[NKV];
__device__ float g_k[NKV];
__device__ float g_v[NKV];
__device__ float g_attn[M_*C_];
__device__ float g_xr[M_*C_];        // tf32-rounded x
__device__ float g_wqkvr[C_*N1_];    // tf32-rounded W_qkv
__device__ float g_woutr[C_*C_];     // tf32-rounded W_out

// ---------------------------------------------------------------------------
// Helpers (family-portable: cp.async + mma.sync only; tcgen05 unavailable
// because PTX targets compute_103 without the 'a' feature set)
// ---------------------------------------------------------------------------
__device__ __forceinline__ uint32_t smem_u32(const void* p) {
    uint32_t a;
    asm("{ .reg .u64 t; cvta.to.shared.u64 t, %1; cvt.u32.u64 %0, t; }"
        : "=r"(a) : "l"(p));
    return a;
}
__device__ __forceinline__ void cpasync16(uint32_t dst, const void* src) {
    asm volatile("cp.async.cg.shared.global [%0], [%1], 16;"
                 :: "r"(dst), "l"(src) : "memory");
}
__device__ __forceinline__ float tfr(float x) {
    float y;
    asm("cvt.rna.tf32.f32 %0, %1;" : "=f"(y) : "f"(x));
    return y;
}
__device__ __forceinline__ void mma_tf32(float* d, const uint32_t* a,
                                         const uint32_t* b) {
    asm volatile(
        "mma.sync.aligned.m16n8k8.row.col.f32.tf32.tf32.f32 "
        "{%0,%1,%2,%3}, {%4,%5,%6,%7}, {%8,%9}, {%0,%1,%2,%3};"
        : "+f"(d[0]), "+f"(d[1]), "+f"(d[2]), "+f"(d[3])
        : "r"(a[0]), "r"(a[1]), "r"(a[2]), "r"(a[3]), "r"(b[0]), "r"(b[1]));
}
#define FB(x) __float_as_uint(x)

// ---------------------------------------------------------------------------
// Prep: round fp32 -> tf32 (rna) elementwise
// ---------------------------------------------------------------------------
__global__ void round_tf32_kernel(const float* __restrict__ src,
                                  float* __restrict__ dst, int n4)
{
    for (int i = blockIdx.x * blockDim.x + threadIdx.x; i < n4;
         i += gridDim.x * blockDim.x) {
        float4 v = __ldg((const float4*)src + i);
        v.x = tfr(v.x); v.y = tfr(v.y); v.z = tfr(v.z); v.w = tfr(v.w);
        ((float4*)dst)[i] = v;
    }
}

// ---------------------------------------------------------------------------
// tf32 mma.sync GEMM (inputs pre-rounded): C[4096,N] = A @ W + bias
// CTA 128x128, BK=16, 256 threads (8 warps, 4m x 2n, warp tile 32x64).
// MODE 0: scatter into g_q/g_k/g_v; MODE 1: plain store.
// ---------------------------------------------------------------------------
template <int MODE>
__global__ void __launch_bounds__(256) tc_gemm_kernel(
    const float* __restrict__ Ag, const float* __restrict__ Wg,
    const float* __restrict__ bias, float* __restrict__ Cout, int ldW)
{
    __shared__ float As[2][128][20];
    __shared__ float Bs[2][16][136];

    const int tid  = threadIdx.x;
    const int warp = tid >> 5;
    const int lane = tid & 31;
    const int wm = warp & 3;
    const int wn = warp >> 2;
    const int bm = blockIdx.y << 7;
    const int bn = blockIdx.x << 7;
    const int lp = lane & 3;
    const int lg = lane >> 2;

    float acc[2][8][4];
    #pragma unroll
    for (int mt = 0; mt < 2; mt++)
        #pragma unroll
        for (int nt = 0; nt < 8; nt++)
            #pragma unroll
            for (int i = 0; i < 4; i++) acc[mt][nt][i] = 0.f;

    auto load_tiles = [&](int it, int s) {
        #pragma unroll
        for (int i = 0; i < 2; i++) {
            const int lin = tid + 256 * i;
            const int am = lin >> 2, ak = (lin & 3) << 2;
            cpasync16(smem_u32(&As[s][am][ak]),
                      Ag + (size_t)(bm + am) * 2048 + it * 16 + ak);
            const int bk = lin >> 5, bn4 = (lin & 31) << 2;
            cpasync16(smem_u32(&Bs[s][bk][bn4]),
                      Wg + (size_t)(it * 16 + bk) * ldW + bn + bn4);
        }
        asm volatile("cp.async.commit_group;" ::: "memory");
    };

    const int NIT = 2048 / 16;
    load_tiles(0, 0);
    load_tiles(1, 1);

    for (int it = 0; it < NIT; it++) {
        const int cur = it & 1;
        if (it == NIT - 1) asm volatile("cp.async.wait_group 0;" ::: "memory");
        else               asm volatile("cp.async.wait_group 1;" ::: "memory");
        __syncthreads();

        #pragma unroll
        for (int ks = 0; ks < 2; ks++) {
            const int c = ks * 8;
            uint32_t af[2][4];
            #pragma unroll
            for (int mt = 0; mt < 2; mt++) {
                const int r0 = wm * 32 + mt * 16 + lg;
                af[mt][0] = FB(As[cur][r0    ][c + lp]);
                af[mt][1] = FB(As[cur][r0 + 8][c + lp]);
                af[mt][2] = FB(As[cur][r0    ][c + 4 + lp]);
                af[mt][3] = FB(As[cur][r0 + 8][c + 4 + lp]);
            }
            #pragma unroll
            for (int nt = 0; nt < 8; nt++) {
                const int nc = wn * 64 + nt * 8 + lg;
                uint32_t bf[2];
                bf[0] = FB(Bs[cur][c + lp    ][nc]);
                bf[1] = FB(Bs[cur][c + 4 + lp][nc]);
                mma_tf32(acc[0][nt], af[0], bf);
                mma_tf32(acc[1][nt], af[1], bf);
            }
        }
        __syncthreads();
        if (it + 2 < NIT) load_tiles(it + 2, cur);
    }

    #pragma unroll
    for (int mt = 0; mt < 2; mt++) {
        #pragma unroll
        for (int half = 0; half < 2; half++) {
            const int m = bm + wm * 32 + mt * 16 + lg + half * 8;
            #pragma unroll
            for (int nt = 0; nt < 8; nt++) {
                const int d = wn * 64 + nt * 8 + lp * 2;
                const float c0 = acc[mt][nt][half * 2 + 0];
                const float c1 = acc[mt][nt][half * 2 + 1];
                float2 bv = *(const float2*)(bias + bn + d);
                float2 o = make_float2(c0 + bv.x, c1 + bv.y);
                if (MODE == 0) {
                    const int which = bn >> 11;
                    const int h = (bn & 2047) >> 7;
                    const int bi = m >> 11, t = m & 2047;
                    float* base = (which == 0) ? g_q
                                 : ((which == 1) ? g_k : g_v);
                    *(float2*)(base + (((size_t)bi * H_ + h) * T_ + t) * D_ + d) = o;
                } else {
                    *(float2*)(Cout + (size_t)m * 2048 + bn + d) = o;
                }
            }
        }
    }
}

// ---------------------------------------------------------------------------
// Tensor-core flash attention (tf32 mma.sync), causal.
// Br=128, Bc=64, D=128. 8 warps, each owns 16 q-rows (m-split) -> softmax
// reductions are intra-quad shfl only. Padded smem strides make every
// fragment LDS a bank permutation: Qs/Ks 132, Vs 136, Ps 68.
// ---------------------------------------------------------------------------
__global__ void __launch_bounds__(256, 1) attn_tc_kernel()
{
    extern __shared__ float sm[];
    float* Qs = sm;                       // [128][132]
    float* Ks = Qs + 128 * 132;           // [64][132]
    float* Vs = Ks + 64 * 132;            // [64][136]
    float* Ps = Vs + 64 * 136;            // [128][68]

    const int it  = blockIdx.x;           // q tile (128 rows)
    const int bh  = blockIdx.y;
    const int tid = threadIdx.x;
    const int w   = tid >> 5;
    const int lane = tid & 31;
    const int lg = lane >> 2, lp = lane & 3;
    const int r0 = w * 16;

    const float* Qg = g_q + (size_t)bh * (T_ * D_);
    const float* Kg = g_k + (size_t)bh * (T_ * D_);
    const float* Vg = g_v + (size_t)bh * (T_ * D_);

    // Q tile (rounded to tf32)
    {
        const int row = tid >> 1, cb = (tid & 1) * 64;
        #pragma unroll
        for (int j = 0; j < 16; j++) {
            float4 v = *(const float4*)(Qg + (size_t)(it * 128 + row) * 128
                                        + cb + 4 * j);
            v.x = tfr(v.x); v.y = tfr(v.y); v.z = tfr(v.z); v.w = tfr(v.w);
            *(float4*)&Qs[row * 132 + cb + 4 * j] = v;
        }
    }

    float accO[16][4];
    #pragma unroll
    for (int nt = 0; nt < 16; nt++)
        #pragma unroll
        for (int i = 0; i < 4; i++) accO[nt][i] = 0.f;
    float m0 = -INFINITY, m1 = -INFINITY, l0 = 0.f, l1 = 0.f;
    const float scale = 0.08838834764831845f;  // 1/sqrt(128)
    const int jmax = 2 * it + 1;

    for (int jt = 0; jt <= jmax; jt++) {
        __syncthreads();
        {
            const int row = tid >> 2, cb = (tid & 3) * 32;
            #pragma unroll
            for (int j = 0; j < 8; j++) {
                float4 kv = *(const float4*)(Kg + (size_t)(jt * 64 + row) * 128
                                             + cb + 4 * j);
                kv.x = tfr(kv.x); kv.y = tfr(kv.y);
                kv.z = tfr(kv.z); kv.w = tfr(kv.w);
                *(float4*)&Ks[row * 132 + cb + 4 * j] = kv;
                float4 vv = *(const float4*)(Vg + (size_t)(jt * 64 + row) * 128
                                             + cb + 4 * j);
                vv.x = tfr(vv.x); vv.y = tfr(vv.y);
                vv.z = tfr(vv.z); vv.w = tfr(vv.w);
                *(float4*)&Vs[row * 136 + cb + 4 * j] = vv;
            }
        }
        __syncthreads();

        // ---- S = Q K^T : 8 n-tiles (64 keys), 16 k-steps (D=128)
        float accS[8][4];
        #pragma unroll
        for (int nt = 0; nt < 8; nt++)
            #pragma unroll
            for (int i = 0; i < 4; i++) accS[nt][i] = 0.f;

        #pragma unroll
        for (int s = 0; s < 16; s++) {
            uint32_t a[4];
            a[0] = FB(Qs[(r0 + lg)     * 132 + 8 * s + lp]);
            a[1] = FB(Qs[(r0 + lg + 8) * 132 + 8 * s + lp]);
            a[2] = FB(Qs[(r0 + lg)     * 132 + 8 * s + lp + 4]);
            a[3] = FB(Qs[(r0 + lg + 8) * 132 + 8 * s + lp + 4]);
            #pragma unroll
            for (int nt = 0; nt < 8; nt++) {
                uint32_t b[2];
                b[0] = FB(Ks[(8 * nt + lg) * 132 + 8 * s + lp]);
                b[1] = FB(Ks[(8 * nt + lg) * 132 + 8 * s + lp + 4]);
                mma_tf32(accS[nt], a, b);
            }
        }

        // ---- scale + causal mask
        const int rq0 = it * 128 + r0 + lg;
        const int rq1 = rq0 + 8;
        if (jt >= 2 * it) {
            #pragma unroll
            for (int nt = 0; nt < 8; nt++) {
                #pragma unroll
                for (int jj = 0; jj < 2; jj++) {
                    const int ck = jt * 64 + 8 * nt + 2 * lp + jj;
                    accS[nt][jj]     = (ck > rq0) ? -INFINITY
                                                  : accS[nt][jj] * scale;
                    accS[nt][jj + 2] = (ck > rq1) ? -INFINITY
                                                  : accS[nt][jj + 2] * scale;
                }
            }
        } else {
            #pragma unroll
            for (int nt = 0; nt < 8; nt++)
                #pragma unroll
                for (int i = 0; i < 4; i++) accS[nt][i] *= scale;
        }

        // ---- online softmax (rows lg and lg+8; quad shfl reductions)
        float mx0 = -INFINITY, mx1 = -INFINITY;
        #pragma unroll
        for (int nt = 0; nt < 8; nt++) {
            mx0 = fmaxf(mx0, fmaxf(accS[nt][0], accS[nt][1]));
            mx1 = fmaxf(mx1, fmaxf(accS[nt][2], accS[nt][3]));
        }
        mx0 = fmaxf(mx0, __shfl_xor_sync(0xffffffffu, mx0, 1));
        mx0 = fmaxf(mx0, __shfl_xor_sync(0xffffffffu, mx0, 2));
        mx1 = fmaxf(mx1, __shfl_xor_sync(0xffffffffu, mx1, 1));
        mx1 = fmaxf(mx1, __shfl_xor_sync(0xffffffffu, mx1, 2));
        const float mn0 = fmaxf(m0, mx0), mn1 = fmaxf(m1, mx1);
        const float al0 = __expf(m0 - mn0), al1 = __expf(m1 - mn1);
        float s0 = 0.f, s1 = 0.f;
        #pragma unroll
        for (int nt = 0; nt < 8; nt++) {
            float p;
            p = __expf(accS[nt][0] - mn0); accS[nt][0] = p; s0 += p;
            p = __expf(accS[nt][1] - mn0); accS[nt][1] = p; s0 += p;
            p = __expf(accS[nt][2] - mn1); accS[nt][2] = p; s1 += p;
            p = __expf(accS[nt][3] - mn1); accS[nt][3] = p; s1 += p;
        }
        s0 += __shfl_xor_sync(0xffffffffu, s0, 1);
        s0 += __shfl_xor_sync(0xffffffffu, s0, 2);
        s1 += __shfl_xor_sync(0xffffffffu, s1, 1);
        s1 += __shfl_xor_sync(0xffffffffu, s1, 2);
        l0 = l0 * al0 + s0; m0 = mn0;
        l1 = l1 * al1 + s1; m1 = mn1;
        #pragma unroll
        for (int nt = 0; nt < 16; nt++) {
            accO[nt][0] *= al0; accO[nt][1] *= al0;
            accO[nt][2] *= al1; accO[nt][3] *= al1;
        }
        // P -> smem (rounded), rows are warp-private
        #pragma unroll
        for (int nt = 0; nt < 8; nt++) {
            float2 p0 = make_float2(tfr(accS[nt][0]), tfr(accS[nt][1]));
            float2 p1 = make_float2(tfr(accS[nt][2]), tfr(accS[nt][3]));
            *(float2*)&Ps[(r0 + lg)     * 68 + 8 * nt + 2 * lp] = p0;
            *(float2*)&Ps[(r0 + lg + 8) * 68 + 8 * nt + 2 * lp] = p1;
        }
        __syncwarp();

        // ---- O += P V : 16 n-tiles (D=128), 8 k-steps (64 keys)
        #pragma unroll
        for (int s = 0; s < 8; s++) {
            uint32_t a[4];
            a[0] = FB(Ps[(r0 + lg)     * 68 + 8 * s + lp]);
            a[1] = FB(Ps[(r0 + lg + 8) * 68 + 8 * s + lp]);
            a[2] = FB(Ps[(r0 + lg)     * 68 + 8 * s + lp + 4]);
            a[3] = FB(Ps[(r0 + lg + 8) * 68 + 8 * s + lp + 4]);
            #pragma unroll
            for (int nt = 0; nt < 16; nt++) {
                uint32_t b[2];
                b[0] = FB(Vs[(8 * s + lp)     * 136 + 8 * nt + lg]);
                b[1] = FB(Vs[(8 * s + lp + 4) * 136 + 8 * nt + lg]);
                mma_tf32(accO[nt], a, b);
            }
        }
    }

    // ---- epilogue: normalize, round to tf32 (feeds out-proj GEMM), store
    const int bi = bh >> 4, h = bh & 15;
    const float inv0 = 1.0f / l0, inv1 = 1.0f / l1;
    const int row0 = it * 128 + r0 + lg;
    #pragma unroll
    for (int nt = 0; nt < 16; nt++) {
        const int d = 8 * nt + 2 * lp;
        float2 o0 = make_float2(tfr(accO[nt][0] * inv0),
                                tfr(accO[nt][1] * inv0));
        float2 o1 = make_float2(tfr(accO[nt][2] * inv1),
                                tfr(accO[nt][3] * inv1));
        *(float2*)(g_attn + ((size_t)bi * T_ + row0) * C_ + h * 128 + d) = o0;
        *(float2*)(g_attn + ((size_t)bi * T_ + row0 + 8) * C_ + h * 128 + d) = o1;
    }
}

// ---------------------------------------------------------------------------
// Launch
// ---------------------------------------------------------------------------
extern "C" void kernel_launch(void* const* d_in, const int* in_sizes, int n_in,
                              void* d_out, int out_size)
{
    const float* x = nullptr;
    const float* W_qkv = nullptr;
    const float* b_qkv = nullptr;
    const float* W_out = nullptr;
    const float* b_out = nullptr;
    int n4m_seen = 0;
    for (int i = 0; i < n_in; i++) {
        const int sz = in_sizes[i];
        if (sz == M_ * C_ && x == nullptr) x = (const float*)d_in[i];
        else if (sz == C_ * N1_) W_qkv = (const float*)d_in[i];
        else if (sz == N1_) b_qkv = (const float*)d_in[i];
        else if (sz == C_ * C_) {
            if (n4m_seen == 1) W_out = (const float*)d_in[i];
            n4m_seen++;
        }
        else if (sz == C_) b_out = (const float*)d_in[i];
    }
    float* out = (float*)d_out;

    void *xr, *wqkvr, *woutr, *attn_ptr;
    cudaGetSymbolAddress(&xr, g_xr);
    cudaGetSymbolAddress(&wqkvr, g_wqkvr);
    cudaGetSymbolAddress(&woutr, g_woutr);
    cudaGetSymbolAddress(&attn_ptr, g_attn);

    const int ATTN_SMEM = (128*132 + 64*132 + 64*136 + 128*68) * 4; // 171008
    cudaFuncSetAttribute(attn_tc_kernel,
                         cudaFuncAttributeMaxDynamicSharedMemorySize, ATTN_SMEM);

    // Pre-round inputs to tf32 (removes all cvt from GEMM hot loops)
    round_tf32_kernel<<<592, 256>>>(x, (float*)xr, (M_*C_)/4);
    round_tf32_kernel<<<592, 256>>>(W_qkv, (float*)wqkvr, (C_*N1_)/4);
    round_tf32_kernel<<<592, 256>>>(W_out, (float*)woutr, (C_*C_)/4);

    // qkv: N=6144 -> 48 x 32 CTAs
    tc_gemm_kernel<0><<<dim3(48, 32), 256>>>((const float*)xr,
                                             (const float*)wqkvr,
                                             b_qkv, nullptr, 6144);
    // attention: 16 q-tiles x 32 (b,h)
    attn_tc_kernel<<<dim3(16, 32), 256, ATTN_SMEM>>>();
    // out proj: N=2048 -> 16 x 32 CTAs
    tc_gemm_kernel<1><<<dim3(16, 32), 256>>>((const float*)attn_ptr,
                                             (const float*)woutr,
                                             b_out, out, 2048);

    const size_t nbytes = (size_t)NKV * sizeof(float);
    if (out_size >= 2 * NKV)
        cudaMemcpyFromSymbolAsync(out + NKV, g_k, nbytes, 0,
                                  cudaMemcpyDeviceToDevice, 0);
    if (out_size >= 3 * NKV)
        cudaMemcpyFromSymbolAsync(out + 2 * NKV, g_v, nbytes, 0,
                                  cudaMemcpyDeviceToDevice, 0);
}

// round 5
// speedup vs baseline: 6.8780x; 2.0763x over previous
#include <cuda_runtime.h>
#include <cuda_fp16.h>
#include <math.h>
#include <stdint.h>

#define B_ 2
#define T_ 2048
#define C_ 2048
#define H_ 16
#define D_ 128
#define M_ (B_*T_)            /* 4096 */
#define N1_ (3*C_)            /* 6144 */
#define NKV (B_*H_*T_*D_)     /* 8388608 */

// Scratch (allocation-free)
__device__ __half g_xh[M_*C_];       // x  fp16
__device__ __half g_wqkvt[N1_*C_];   // W_qkv^T [n][k] fp16
__device__ __half g_woutt[C_*C_];    // W_out^T [n][k] fp16
__device__ __half g_qh[NKV];
__device__ __half g_kh[NKV];
__device__ __half g_vh[NKV];
__device__ float  g_k[NKV];          // fp32 k (output fidelity)
__device__ float  g_v[NKV];          // fp32 v
__device__ __half g_attnh[M_*C_];    // attention out fp16

// ---------------------------------------------------------------------------
// Helpers (family-portable: cp.async, ldmatrix, mma.sync fp16)
// ---------------------------------------------------------------------------
__device__ __forceinline__ uint32_t smem_u32(const void* p) {
    uint32_t a;
    asm("{ .reg .u64 t; cvta.to.shared.u64 t, %1; cvt.u32.u64 %0, t; }"
        : "=r"(a) : "l"(p));
    return a;
}
__device__ __forceinline__ void cpasync16(uint32_t dst, const void* src) {
    asm volatile("cp.async.cg.shared.global [%0], [%1], 16;"
                 :: "r"(dst), "l"(src) : "memory");
}
#define CP_COMMIT() asm volatile("cp.async.commit_group;" ::: "memory")
__device__ __forceinline__ void ldsm4(uint32_t* r, uint32_t a) {
    asm volatile("ldmatrix.sync.aligned.m8n8.x4.shared.b16 {%0,%1,%2,%3}, [%4];"
                 : "=r"(r[0]), "=r"(r[1]), "=r"(r[2]), "=r"(r[3]) : "r"(a));
}
__device__ __forceinline__ void ldsm4t(uint32_t* r, uint32_t a) {
    asm volatile("ldmatrix.sync.aligned.m8n8.x4.trans.shared.b16 {%0,%1,%2,%3}, [%4];"
                 : "=r"(r[0]), "=r"(r[1]), "=r"(r[2]), "=r"(r[3]) : "r"(a));
}
__device__ __forceinline__ void mma16(float* d, const uint32_t* a,
                                      const uint32_t* b) {
    asm volatile(
        "mma.sync.aligned.m16n8k16.row.col.f32.f16.f16.f32 "
        "{%0,%1,%2,%3}, {%4,%5,%6,%7}, {%8,%9}, {%0,%1,%2,%3};"
        : "+f"(d[0]), "+f"(d[1]), "+f"(d[2]), "+f"(d[3])
        : "r"(a[0]), "r"(a[1]), "r"(a[2]), "r"(a[3]), "r"(b[0]), "r"(b[1]));
}
__device__ __forceinline__ uint32_t packh2(float lo, float hi) {
    __half2 h = __floats2half2_rn(lo, hi);
    return *(uint32_t*)&h;
}

// ---------------------------------------------------------------------------
// Prep: fp32 -> fp16 elementwise
// ---------------------------------------------------------------------------
__global__ void cvt_f16_kernel(const float* __restrict__ src,
                               __half* __restrict__ dst, int n4)
{
    for (int i = blockIdx.x * blockDim.x + threadIdx.x; i < n4;
         i += gridDim.x * blockDim.x) {
        float4 v = __ldg((const float4*)src + i);
        uint2 o;
        o.x = packh2(v.x, v.y);
        o.y = packh2(v.z, v.w);
        ((uint2*)dst)[i] = o;
    }
}

// Prep: transpose + convert W[k][n] f32 -> Wt[n][k] f16
__global__ void __launch_bounds__(256) transpose_f16_kernel(
    const float* __restrict__ W, __half* __restrict__ Wt, int K, int N)
{
    __shared__ float tile[32][33];
    const int k0 = blockIdx.y << 5, n0 = blockIdx.x << 5;
    const int tx = threadIdx.x & 31, ty = threadIdx.x >> 5;
    #pragma unroll
    for (int r = 0; r < 4; r++)
        tile[ty + 8 * r][tx] = __ldg(W + (size_t)(k0 + ty + 8 * r) * N + n0 + tx);
    __syncthreads();
    #pragma unroll
    for (int r = 0; r < 4; r++)
        Wt[(size_t)(n0 + ty + 8 * r) * K + k0 + tx] =
            __float2half_rn(tile[tx][ty + 8 * r]);
}

// ---------------------------------------------------------------------------
// fp16 mma.sync GEMM: C[4096,N] = A[4096,2048] @ Wt^T + bias
// A [m][k] f16, Wt [n][k] f16. CTA 128x128, BK=32, 3-stage cp.async,
// 8 warps (4m x 2n, warp tile 32x64). MODE 0: scatter qkv; MODE 1: store f32.
// Smem row stride 40 halves (80B): ldmatrix conflict-free.
// ---------------------------------------------------------------------------
#define GSTG 20480
#define GEMM_SMEM (3 * GSTG)

template <int MODE>
__global__ void __launch_bounds__(256, 2) hgemm_kernel(
    const __half* __restrict__ Ag, const __half* __restrict__ Bt,
    const float* __restrict__ bias, float* __restrict__ Cout)
{
    extern __shared__ char dynsm[];
    const uint32_t smb = smem_u32(dynsm);
    const int tid  = threadIdx.x;
    const int lane = tid & 31;
    const int warp = tid >> 5;
    const int wm = warp & 3, wn = warp >> 2;
    const int bm = blockIdx.y << 7, bn = blockIdx.x << 7;
    const int lg = lane >> 2, lp = lane & 3;

    float acc[2][8][4];
    #pragma unroll
    for (int mt = 0; mt < 2; mt++)
        #pragma unroll
        for (int nt = 0; nt < 8; nt++)
            #pragma unroll
            for (int i = 0; i < 4; i++) acc[mt][nt][i] = 0.f;

    // cp.async tile load: A rows 128 x 32h, B rows 128 x 32h (each 4x16B)
    const int c_row = tid >> 1;               // 0..127
    const int c_sg0 = (tid & 1) << 1;         // 0 or 2
    auto load_tiles = [&](int it, int s) {
        const uint32_t base = smb + s * GSTG;
        #pragma unroll
        for (int j = 0; j < 2; j++) {
            const int seg = c_sg0 + j;
            cpasync16(base + c_row * 80 + seg * 16,
                      Ag + (size_t)(bm + c_row) * 2048 + it * 32 + seg * 8);
            cpasync16(base + 10240 + c_row * 80 + seg * 16,
                      Bt + (size_t)(bn + c_row) * 2048 + it * 32 + seg * 8);
        }
        CP_COMMIT();
    };

    // ldmatrix lane offsets
    const uint32_t a_off = (lane & 15) * 80 + (lane >> 4) * 16;
    const uint32_t b_off = ((lane & 7) + ((lane >> 4) & 1) * 8) * 80
                           + ((lane >> 3) & 1) * 16;

    const int NIT = 2048 / 32;  // 64
    load_tiles(0, 0);
    load_tiles(1, 1);

    for (int it = 0; it < NIT; it++) {
        const int s = it % 3;
        if (it == NIT - 1) asm volatile("cp.async.wait_group 0;" ::: "memory");
        else               asm volatile("cp.async.wait_group 1;" ::: "memory");
        __syncthreads();
        if (it + 2 < NIT) load_tiles(it + 2, (it + 2) % 3);

        const uint32_t smA = smb + s * GSTG;
        const uint32_t smB = smA + 10240;
        #pragma unroll
        for (int ks = 0; ks < 2; ks++) {
            uint32_t a[2][4];
            ldsm4(a[0], smA + (wm * 32 + 0) * 80 + a_off + ks * 32);
            ldsm4(a[1], smA + (wm * 32 + 16) * 80 + a_off + ks * 32);
            #pragma unroll
            for (int np = 0; np < 4; np++) {
                uint32_t b4[4];
                ldsm4(b4, smB + (wn * 64 + np * 16) * 80 + b_off + ks * 32);
                mma16(acc[0][2 * np],     a[0], b4);
                mma16(acc[1][2 * np],     a[1], b4);
                mma16(acc[0][2 * np + 1], a[0], b4 + 2);
                mma16(acc[1][2 * np + 1], a[1], b4 + 2);
            }
        }
    }

    // Epilogue
    #pragma unroll
    for (int mt = 0; mt < 2; mt++) {
        #pragma unroll
        for (int half = 0; half < 2; half++) {
            const int m = bm + wm * 32 + mt * 16 + lg + half * 8;
            #pragma unroll
            for (int nt = 0; nt < 8; nt++) {
                const int n = bn + wn * 64 + nt * 8 + 2 * lp;
                float2 bv = *(const float2*)(bias + n);
                const float o0 = acc[mt][nt][half * 2 + 0] + bv.x;
                const float o1 = acc[mt][nt][half * 2 + 1] + bv.y;
                if (MODE == 0) {
                    const int which = n >> 11;
                    const int h = (n & 2047) >> 7;
                    const int d = n & 127;
                    const int bi = m >> 11, t = m & 2047;
                    const size_t idx = (((size_t)bi * H_ + h) * T_ + t) * D_ + d;
                    const uint32_t p = packh2(o0, o1);
                    if (which == 0) {
                        *(uint32_t*)&g_qh[idx] = p;
                    } else if (which == 1) {
                        *(uint32_t*)&g_kh[idx] = p;
                        *(float2*)&g_k[idx] = make_float2(o0, o1);
                    } else {
                        *(uint32_t*)&g_vh[idx] = p;
                        *(float2*)&g_v[idx] = make_float2(o0, o1);
                    }
                } else {
                    *(float2*)(Cout + (size_t)m * 2048 + n) = make_float2(o0, o1);
                }
            }
        }
    }
}

// ---------------------------------------------------------------------------
// fp16 flash attention, causal. Br=128 (8 warps x 16 rows), Bc=32, D=128.
// K/V double-buffered cp.async (1 sync/iter). S accum fragments are repacked
// directly into P A-fragments (fp16 layout match) -> no P smem.
// Smem row stride 136 halves (272B): ldmatrix conflict-free.
// ---------------------------------------------------------------------------
#define AQ_BYTES (128 * 272)                 /* 34816 */
#define AKV_BYTES (32 * 272)                 /*  8704 */
#define ATTN_SMEM (AQ_BYTES + 4 * AKV_BYTES) /* 69632 */

__global__ void __launch_bounds__(256, 2) attn_tc_kernel()
{
    extern __shared__ char dynsm[];
    const uint32_t smb = smem_u32(dynsm);
    const uint32_t smQ = smb;

    const int it  = (gridDim.x - 1) - blockIdx.x;  // big tiles first
    const int bh  = blockIdx.y;
    const int tid = threadIdx.x;
    const int lane = tid & 31;
    const int w   = tid >> 5;
    const int lg = lane >> 2, lp = lane & 3;
    const int r0 = w * 16;

    const __half* Qg = g_qh + (size_t)bh * (T_ * D_);
    const __half* Kg = g_kh + (size_t)bh * (T_ * D_);
    const __half* Vg = g_vh + (size_t)bh * (T_ * D_);

    // Q: 128 rows x 256B
    {
        const int row = tid >> 1;
        const int s0 = (tid & 1) * 8;
        #pragma unroll
        for (int j = 0; j < 8; j++)
            cpasync16(smQ + row * 272 + (s0 + j) * 16,
                      Qg + (size_t)(it * 128 + row) * 128 + (s0 + j) * 8);
    }
    const int kv_row = tid >> 3;            // 2 segs per thread per matrix
    const int kv_s0 = (tid & 7) * 2;
    auto load_kv = [&](int jt, int st) {
        const uint32_t smK = smb + AQ_BYTES + st * AKV_BYTES;
        const uint32_t smV = smb + AQ_BYTES + 2 * AKV_BYTES + st * AKV_BYTES;
        #pragma unroll
        for (int j = 0; j < 2; j++) {
            const int seg = kv_s0 + j;
            cpasync16(smK + kv_row * 272 + seg * 16,
                      Kg + (size_t)(jt * 32 + kv_row) * 128 + seg * 8);
            cpasync16(smV + kv_row * 272 + seg * 16,
                      Vg + (size_t)(jt * 32 + kv_row) * 128 + seg * 8);
        }
        CP_COMMIT();
    };
    load_kv(0, 0);

    // ldmatrix lane offsets
    const uint32_t q_off = (r0 + (lane & 15)) * 272 + (lane >> 4) * 16;
    const uint32_t k_off = ((lane & 7) + ((lane >> 4) & 1) * 8) * 272
                           + ((lane >> 3) & 1) * 16;
    const uint32_t v_off = ((lane & 7) + ((lane >> 3) & 1) * 8) * 272
                           + (lane >> 4) * 16;

    float accO[16][4];
    #pragma unroll
    for (int nt = 0; nt < 16; nt++)
        #pragma unroll
        for (int i = 0; i < 4; i++) accO[nt][i] = 0.f;
    float m0 = -INFINITY, m1 = -INFINITY, l0 = 0.f, l1 = 0.f;
    const float scale = 0.08838834764831845f;  // 1/sqrt(128)
    const int jmax = 4 * it + 3;
    const int rq0 = it * 128 + r0 + lg;
    const int rq1 = rq0 + 8;

    for (int jt = 0; jt <= jmax; jt++) {
        const int cur = jt & 1;
        asm volatile("cp.async.wait_group 0;" ::: "memory");
        __syncthreads();
        if (jt < jmax) load_kv(jt + 1, cur ^ 1);

        // warp-level skip: all keys beyond all of this warp's rows
        if (jt * 32 > it * 128 + r0 + 15) continue;

        const uint32_t smK = smb + AQ_BYTES + cur * AKV_BYTES;
        const uint32_t smV = smb + AQ_BYTES + 2 * AKV_BYTES + cur * AKV_BYTES;

        // ---- S = Q K^T : 4 n-tiles (32 keys), 8 k-slices (D=128)
        float accS[4][4];
        #pragma unroll
        for (int nt = 0; nt < 4; nt++)
            #pragma unroll
            for (int i = 0; i < 4; i++) accS[nt][i] = 0.f;
        #pragma unroll
        for (int ks = 0; ks < 8; ks++) {
            uint32_t qa[4];
            ldsm4(qa, smQ + q_off + ks * 32);
            #pragma unroll
            for (int np = 0; np < 2; np++) {
                uint32_t kb[4];
                ldsm4(kb, smK + np * 16 * 272 + k_off + ks * 32);
                mma16(accS[2 * np],     qa, kb);
                mma16(accS[2 * np + 1], qa, kb + 2);
            }
        }

        // ---- scale + causal mask
        if (jt * 32 + 31 > it * 128 + r0) {
            #pragma unroll
            for (int nt = 0; nt < 4; nt++) {
                #pragma unroll
                for (int jj = 0; jj < 2; jj++) {
                    const int ck = jt * 32 + 8 * nt + 2 * lp + jj;
                    accS[nt][jj]     = (ck > rq0) ? -INFINITY
                                                  : accS[nt][jj] * scale;
                    accS[nt][jj + 2] = (ck > rq1) ? -INFINITY
                                                  : accS[nt][jj + 2] * scale;
                }
            }
        } else {
            #pragma unroll
            for (int nt = 0; nt < 4; nt++)
                #pragma unroll
                for (int i = 0; i < 4; i++) accS[nt][i] *= scale;
        }

        // ---- online softmax (rows rq0, rq1; quad shfl reductions)
        float mx0 = -INFINITY, mx1 = -INFINITY;
        #pragma unroll
        for (int nt = 0; nt < 4; nt++) {
            mx0 = fmaxf(mx0, fmaxf(accS[nt][0], accS[nt][1]));
            mx1 = fmaxf(mx1, fmaxf(accS[nt][2], accS[nt][3]));
        }
        mx0 = fmaxf(mx0, __shfl_xor_sync(0xffffffffu, mx0, 1));
        mx0 = fmaxf(mx0, __shfl_xor_sync(0xffffffffu, mx0, 2));
        mx1 = fmaxf(mx1, __shfl_xor_sync(0xffffffffu, mx1, 1));
        mx1 = fmaxf(mx1, __shfl_xor_sync(0xffffffffu, mx1, 2));
        const float mn0 = fmaxf(m0, mx0), mn1 = fmaxf(m1, mx1);
        const float al0 = __expf(m0 - mn0), al1 = __expf(m1 - mn1);
        float s0 = 0.f, s1 = 0.f;
        #pragma unroll
        for (int nt = 0; nt < 4; nt++) {
            float p;
            p = __expf(accS[nt][0] - mn0); accS[nt][0] = p; s0 += p;
            p = __expf(accS[nt][1] - mn0); accS[nt][1] = p; s0 += p;
            p = __expf(accS[nt][2] - mn1); accS[nt][2] = p; s1 += p;
            p = __expf(accS[nt][3] - mn1); accS[nt][3] = p; s1 += p;
        }
        s0 += __shfl_xor_sync(0xffffffffu, s0, 1);
        s0 += __shfl_xor_sync(0xffffffffu, s0, 2);
        s1 += __shfl_xor_sync(0xffffffffu, s1, 1);
        s1 += __shfl_xor_sync(0xffffffffu, s1, 2);
        l0 = l0 * al0 + s0; m0 = mn0;
        l1 = l1 * al1 + s1; m1 = mn1;
        #pragma unroll
        for (int nt = 0; nt < 16; nt++) {
            accO[nt][0] *= al0; accO[nt][1] *= al0;
            accO[nt][2] *= al1; accO[nt][3] *= al1;
        }

        // ---- O += P V : P a-frags packed directly from accS
        #pragma unroll
        for (int s = 0; s < 2; s++) {
            uint32_t pa[4];
            pa[0] = packh2(accS[2 * s][0], accS[2 * s][1]);
            pa[1] = packh2(accS[2 * s][2], accS[2 * s][3]);
            pa[2] = packh2(accS[2 * s + 1][0], accS[2 * s + 1][1]);
            pa[3] = packh2(accS[2 * s + 1][2], accS[2 * s + 1][3]);
            #pragma unroll
            for (int np = 0; np < 8; np++) {
                uint32_t vb[4];
                ldsm4t(vb, smV + s * 16 * 272 + v_off + np * 32);
                mma16(accO[2 * np],     pa, vb);
                mma16(accO[2 * np + 1], pa, vb + 2);
            }
        }
    }

    // ---- epilogue: normalize, fp16 pack -> g_attnh [B,T,C]
    const int bi = bh >> 4, h = bh & 15;
    const float inv0 = 1.0f / l0, inv1 = 1.0f / l1;
    const int row0 = it * 128 + r0 + lg;
    #pragma unroll
    for (int nt = 0; nt < 16; nt++) {
        const int d = 8 * nt + 2 * lp;
        *(uint32_t*)&g_attnh[((size_t)bi * T_ + row0) * C_ + h * 128 + d] =
            packh2(accO[nt][0] * inv0, accO[nt][1] * inv0);
        *(uint32_t*)&g_attnh[((size_t)bi * T_ + row0 + 8) * C_ + h * 128 + d] =
            packh2(accO[nt][2] * inv1, accO[nt][3] * inv1);
    }
}

// ---------------------------------------------------------------------------
// Launch
// ---------------------------------------------------------------------------
extern "C" void kernel_launch(void* const* d_in, const int* in_sizes, int n_in,
                              void* d_out, int out_size)
{
    const float* x = nullptr;
    const float* W_qkv = nullptr;
    const float* b_qkv = nullptr;
    const float* W_out = nullptr;
    const float* b_out = nullptr;
    int n4m_seen = 0;
    for (int i = 0; i < n_in; i++) {
        const int sz = in_sizes[i];
        if (sz == M_ * C_ && x == nullptr) x = (const float*)d_in[i];
        else if (sz == C_ * N1_) W_qkv = (const float*)d_in[i];
        else if (sz == N1_) b_qkv = (const float*)d_in[i];
        else if (sz == C_ * C_) {
            if (n4m_seen == 1) W_out = (const float*)d_in[i];
            n4m_seen++;
        }
        else if (sz == C_) b_out = (const float*)d_in[i];
    }
    float* out = (float*)d_out;

    void *xh, *wqkvt, *woutt, *attnh;
    cudaGetSymbolAddress(&xh, g_xh);
    cudaGetSymbolAddress(&wqkvt, g_wqkvt);
    cudaGetSymbolAddress(&woutt, g_woutt);
    cudaGetSymbolAddress(&attnh, g_attnh);

    cudaFuncSetAttribute(hgemm_kernel<0>,
                         cudaFuncAttributeMaxDynamicSharedMemorySize, GEMM_SMEM);
    cudaFuncSetAttribute(hgemm_kernel<1>,
                         cudaFuncAttributeMaxDynamicSharedMemorySize, GEMM_SMEM);
    cudaFuncSetAttribute(attn_tc_kernel,
                         cudaFuncAttributeMaxDynamicSharedMemorySize, ATTN_SMEM);

    // Prep: fp16 conversions / transposes
    cvt_f16_kernel<<<1184, 256>>>(x, (__half*)xh, (M_ * C_) / 4);
    transpose_f16_kernel<<<dim3(N1_ / 32, C_ / 32), 256>>>(
        W_qkv, (__half*)wqkvt, C_, N1_);
    transpose_f16_kernel<<<dim3(C_ / 32, C_ / 32), 256>>>(
        W_out, (__half*)woutt, C_, C_);

    // qkv: N=6144 -> 48 x 32 CTAs
    hgemm_kernel<0><<<dim3(48, 32), 256, GEMM_SMEM>>>(
        (const __half*)xh, (const __half*)wqkvt, b_qkv, nullptr);
    // attention: 16 q-tiles x 32 (b,h)
    attn_tc_kernel<<<dim3(16, 32), 256, ATTN_SMEM>>>();
    // out proj: N=2048 -> 16 x 32 CTAs
    hgemm_kernel<1><<<dim3(16, 32), 256, GEMM_SMEM>>>(
        (const __half*)attnh, (const __half*)woutt, b_out, out);

    const size_t nbytes = (size_t)NKV * sizeof(float);
    if (out_size >= 2 * NKV)
        cudaMemcpyFromSymbolAsync(out + NKV, g_k, nbytes, 0,
                                  cudaMemcpyDeviceToDevice, 0);
    if (out_size >= 3 * NKV)
        cudaMemcpyFromSymbolAsync(out + 2 * NKV, g_v, nbytes, 0,
                                  cudaMemcpyDeviceToDevice, 0);
}

// round 6
// speedup vs baseline: 7.0301x; 1.0221x over previous
#include <cuda_runtime.h>
#include <cuda_fp16.h>
#include <math.h>
#include <stdint.h>

#define B_ 2
#define T_ 2048
#define C_ 2048
#define H_ 16
#define D_ 128
#define M_ (B_*T_)            /* 4096 */
#define N1_ (3*C_)            /* 6144 */
#define NKV (B_*H_*T_*D_)     /* 8388608 */

// Scratch (allocation-free)
__device__ __half g_xh[M_*C_];       // x  fp16
__device__ __half g_wqkvt[N1_*C_];   // W_qkv^T [n][k] fp16
__device__ __half g_woutt[C_*C_];    // W_out^T [n][k] fp16
__device__ __half g_qh[NKV];
__device__ __half g_kh[NKV];
__device__ __half g_vh[NKV];
__device__ float  g_k[NKV];          // fp32 k (output fidelity)
__device__ float  g_v[NKV];          // fp32 v
__device__ __half g_attnh[M_*C_];    // attention out fp16

// ---------------------------------------------------------------------------
// Helpers
// ---------------------------------------------------------------------------
__device__ __forceinline__ uint32_t smem_u32(const void* p) {
    uint32_t a;
    asm("{ .reg .u64 t; cvta.to.shared.u64 t, %1; cvt.u32.u64 %0, t; }"
        : "=r"(a) : "l"(p));
    return a;
}
__device__ __forceinline__ void cpasync16(uint32_t dst, const void* src) {
    asm volatile("cp.async.cg.shared.global [%0], [%1], 16;"
                 :: "r"(dst), "l"(src) : "memory");
}
#define CP_COMMIT() asm volatile("cp.async.commit_group;" ::: "memory")
__device__ __forceinline__ void ldsm4(uint32_t* r, uint32_t a) {
    asm volatile("ldmatrix.sync.aligned.m8n8.x4.shared.b16 {%0,%1,%2,%3}, [%4];"
                 : "=r"(r[0]), "=r"(r[1]), "=r"(r[2]), "=r"(r[3]) : "r"(a));
}
__device__ __forceinline__ void ldsm4t(uint32_t* r, uint32_t a) {
    asm volatile("ldmatrix.sync.aligned.m8n8.x4.trans.shared.b16 {%0,%1,%2,%3}, [%4];"
                 : "=r"(r[0]), "=r"(r[1]), "=r"(r[2]), "=r"(r[3]) : "r"(a));
}
__device__ __forceinline__ void mma16(float* d, const uint32_t* a,
                                      const uint32_t* b) {
    asm volatile(
        "mma.sync.aligned.m16n8k16.row.col.f32.f16.f16.f32 "
        "{%0,%1,%2,%3}, {%4,%5,%6,%7}, {%8,%9}, {%0,%1,%2,%3};"
        : "+f"(d[0]), "+f"(d[1]), "+f"(d[2]), "+f"(d[3])
        : "r"(a[0]), "r"(a[1]), "r"(a[2]), "r"(a[3]), "r"(b[0]), "r"(b[1]));
}
__device__ __forceinline__ uint32_t packh2(float lo, float hi) {
    __half2 h = __floats2half2_rn(lo, hi);
    return *(uint32_t*)&h;
}

// ---------------------------------------------------------------------------
// Prep kernels
// ---------------------------------------------------------------------------
__global__ void cvt_f16_kernel(const float* __restrict__ src,
                               __half* __restrict__ dst, int n4)
{
    for (int i = blockIdx.x * blockDim.x + threadIdx.x; i < n4;
         i += gridDim.x * blockDim.x) {
        float4 v = __ldg((const float4*)src + i);
        uint2 o;
        o.x = packh2(v.x, v.y);
        o.y = packh2(v.z, v.w);
        ((uint2*)dst)[i] = o;
    }
}

__global__ void __launch_bounds__(256) transpose_f16_kernel(
    const float* __restrict__ W, __half* __restrict__ Wt, int K, int N)
{
    __shared__ float tile[32][33];
    const int k0 = blockIdx.y << 5, n0 = blockIdx.x << 5;
    const int tx = threadIdx.x & 31, ty = threadIdx.x >> 5;
    #pragma unroll
    for (int r = 0; r < 4; r++)
        tile[ty + 8 * r][tx] = __ldg(W + (size_t)(k0 + ty + 8 * r) * N + n0 + tx);
    __syncthreads();
    #pragma unroll
    for (int r = 0; r < 4; r++)
        Wt[(size_t)(n0 + ty + 8 * r) * K + k0 + tx] =
            __float2half_rn(tile[tx][ty + 8 * r]);
}

// ---------------------------------------------------------------------------
// fp16 mma.sync GEMM: C[4096,N] = A @ Wt^T + bias. CTA 128x128, BK=32,
// 5-stage cp.async, __syncthreads every 2 iters, full fragment prefetch.
// 8 warps (4m x 2n, warp tile 32x64). Smem row stride 80B (conflict-free).
// ---------------------------------------------------------------------------
#define GSTG 20480
#define GEMM_SMEM (5 * GSTG)

template <int MODE>
__global__ void __launch_bounds__(256, 2) hgemm_kernel(
    const __half* __restrict__ Ag, const __half* __restrict__ Bt,
    const float* __restrict__ bias, float* __restrict__ Cout)
{
    extern __shared__ char dynsm[];
    const uint32_t smb = smem_u32(dynsm);
    const int tid  = threadIdx.x;
    const int lane = tid & 31;
    const int warp = tid >> 5;
    const int wm = warp & 3, wn = warp >> 2;
    const int bm = blockIdx.y << 7, bn = blockIdx.x << 7;
    const int lg = lane >> 2, lp = lane & 3;

    float acc[2][8][4];
    #pragma unroll
    for (int mt = 0; mt < 2; mt++)
        #pragma unroll
        for (int nt = 0; nt < 8; nt++)
            #pragma unroll
            for (int i = 0; i < 4; i++) acc[mt][nt][i] = 0.f;

    const int c_row = tid >> 1;
    const int c_sg0 = (tid & 1) << 1;
    auto load_tiles = [&](int it, int s) {
        const uint32_t base = smb + s * GSTG;
        #pragma unroll
        for (int j = 0; j < 2; j++) {
            const int seg = c_sg0 + j;
            cpasync16(base + c_row * 80 + seg * 16,
                      Ag + (size_t)(bm + c_row) * 2048 + it * 32 + seg * 8);
            cpasync16(base + 10240 + c_row * 80 + seg * 16,
                      Bt + (size_t)(bn + c_row) * 2048 + it * 32 + seg * 8);
        }
        CP_COMMIT();
    };

    const uint32_t a_off = (lane & 15) * 80 + (lane >> 4) * 16;
    const uint32_t b_off = ((lane & 7) + ((lane >> 4) & 1) * 8) * 80
                           + ((lane >> 3) & 1) * 16;

    // Per-stage compute: prefetch ALL fragments (both k-slices), then 32 mma.
    auto compute_stage = [&](int s) {
        const uint32_t smA = smb + s * GSTG + wm * 32 * 80 + a_off;
        const uint32_t smB = smb + s * GSTG + 10240 + wn * 64 * 80 + b_off;
        uint32_t a[2][2][4], b[2][4][4];
        #pragma unroll
        for (int ks = 0; ks < 2; ks++) {
            ldsm4(a[ks][0], smA + ks * 32);
            ldsm4(a[ks][1], smA + 16 * 80 + ks * 32);
            #pragma unroll
            for (int np = 0; np < 4; np++)
                ldsm4(b[ks][np], smB + np * 16 * 80 + ks * 32);
        }
        #pragma unroll
        for (int ks = 0; ks < 2; ks++) {
            #pragma unroll
            for (int np = 0; np < 4; np++) {
                mma16(acc[0][2 * np],     a[ks][0], b[ks][np]);
                mma16(acc[1][2 * np],     a[ks][1], b[ks][np]);
                mma16(acc[0][2 * np + 1], a[ks][0], b[ks][np] + 2);
                mma16(acc[1][2 * np + 1], a[ks][1], b[ks][np] + 2);
            }
        }
    };

    const int NIT = 2048 / 32;  // 64
    load_tiles(0, 0);
    load_tiles(1, 1);
    load_tiles(2, 2);

    #pragma unroll 1
    for (int t = 0; t < NIT / 2; t++) {
        const int it = 2 * t;
        if (t == NIT / 2 - 1)
            asm volatile("cp.async.wait_group 0;" ::: "memory");
        else
            asm volatile("cp.async.wait_group 1;" ::: "memory");
        __syncthreads();
        if (it + 3 < NIT) load_tiles(it + 3, (it + 3) % 5);
        if (it + 4 < NIT) load_tiles(it + 4, (it + 4) % 5);
        compute_stage(it % 5);
        compute_stage((it + 1) % 5);
    }

    // Epilogue
    #pragma unroll
    for (int mt = 0; mt < 2; mt++) {
        #pragma unroll
        for (int half = 0; half < 2; half++) {
            const int m = bm + wm * 32 + mt * 16 + lg + half * 8;
            #pragma unroll
            for (int nt = 0; nt < 8; nt++) {
                const int n = bn + wn * 64 + nt * 8 + 2 * lp;
                float2 bv = *(const float2*)(bias + n);
                const float o0 = acc[mt][nt][half * 2 + 0] + bv.x;
                const float o1 = acc[mt][nt][half * 2 + 1] + bv.y;
                if (MODE == 0) {
                    const int which = n >> 11;
                    const int h = (n & 2047) >> 7;
                    const int d = n & 127;
                    const int bi = m >> 11, t2 = m & 2047;
                    const size_t idx = (((size_t)bi * H_ + h) * T_ + t2) * D_ + d;
                    const uint32_t p = packh2(o0, o1);
                    if (which == 0) {
                        *(uint32_t*)&g_qh[idx] = p;
                    } else if (which == 1) {
                        *(uint32_t*)&g_kh[idx] = p;
                        *(float2*)&g_k[idx] = make_float2(o0, o1);
                    } else {
                        *(uint32_t*)&g_vh[idx] = p;
                        *(float2*)&g_v[idx] = make_float2(o0, o1);
                    }
                } else {
                    *(float2*)(Cout + (size_t)m * 2048 + n) = make_float2(o0, o1);
                }
            }
        }
    }
}

// ---------------------------------------------------------------------------
// fp16 flash attention, causal. Br=128 (8 warps x 16 rows), Bc=32, D=128.
// ---------------------------------------------------------------------------
#define AQ_BYTES (128 * 272)
#define AKV_BYTES (32 * 272)
#define ATTN_SMEM (AQ_BYTES + 4 * AKV_BYTES)

__global__ void __launch_bounds__(256, 2) attn_tc_kernel()
{
    extern __shared__ char dynsm[];
    const uint32_t smb = smem_u32(dynsm);
    const uint32_t smQ = smb;

    const int it  = (gridDim.x - 1) - blockIdx.x;
    const int bh  = blockIdx.y;
    const int tid = threadIdx.x;
    const int lane = tid & 31;
    const int w   = tid >> 5;
    const int lg = lane >> 2, lp = lane & 3;
    const int r0 = w * 16;

    const __half* Qg = g_qh + (size_t)bh * (T_ * D_);
    const __half* Kg = g_kh + (size_t)bh * (T_ * D_);
    const __half* Vg = g_vh + (size_t)bh * (T_ * D_);

    {
        const int row = tid >> 1;
        const int s0 = (tid & 1) * 8;
        #pragma unroll
        for (int j = 0; j < 8; j++)
            cpasync16(smQ + row * 272 + (s0 + j) * 16,
                      Qg + (size_t)(it * 128 + row) * 128 + (s0 + j) * 8);
    }
    const int kv_row = tid >> 3;
    const int kv_s0 = (tid & 7) * 2;
    auto load_kv = [&](int jt, int st) {
        const uint32_t smK = smb + AQ_BYTES + st * AKV_BYTES;
        const uint32_t smV = smb + AQ_BYTES + 2 * AKV_BYTES + st * AKV_BYTES;
        #pragma unroll
        for (int j = 0; j < 2; j++) {
            const int seg = kv_s0 + j;
            cpasync16(smK + kv_row * 272 + seg * 16,
                      Kg + (size_t)(jt * 32 + kv_row) * 128 + seg * 8);
            cpasync16(smV + kv_row * 272 + seg * 16,
                      Vg + (size_t)(jt * 32 + kv_row) * 128 + seg * 8);
        }
        CP_COMMIT();
    };
    load_kv(0, 0);

    const uint32_t q_off = (r0 + (lane & 15)) * 272 + (lane >> 4) * 16;
    const uint32_t k_off = ((lane & 7) + ((lane >> 4) & 1) * 8) * 272
                           + ((lane >> 3) & 1) * 16;
    const uint32_t v_off = ((lane & 7) + ((lane >> 3) & 1) * 8) * 272
                           + (lane >> 4) * 16;

    float accO[16][4];
    #pragma unroll
    for (int nt = 0; nt < 16; nt++)
        #pragma unroll
        for (int i = 0; i < 4; i++) accO[nt][i] = 0.f;
    float m0 = -INFINITY, m1 = -INFINITY, l0 = 0.f, l1 = 0.f;
    const float scale = 0.08838834764831845f;
    const int jmax = 4 * it + 3;
    const int rq0 = it * 128 + r0 + lg;
    const int rq1 = rq0 + 8;

    for (int jt = 0; jt <= jmax; jt++) {
        const int cur = jt & 1;
        asm volatile("cp.async.wait_group 0;" ::: "memory");
        __syncthreads();
        if (jt < jmax) load_kv(jt + 1, cur ^ 1);

        if (jt * 32 > it * 128 + r0 + 15) continue;

        const uint32_t smK = smb + AQ_BYTES + cur * AKV_BYTES;
        const uint32_t smV = smb + AQ_BYTES + 2 * AKV_BYTES + cur * AKV_BYTES;

        float accS[4][4];
        #pragma unroll
        for (int nt = 0; nt < 4; nt++)
            #pragma unroll
            for (int i = 0; i < 4; i++) accS[nt][i] = 0.f;
        #pragma unroll
        for (int ks = 0; ks < 8; ks++) {
            uint32_t qa[4];
            ldsm4(qa, smQ + q_off + ks * 32);
            #pragma unroll
            for (int np = 0; np < 2; np++) {
                uint32_t kb[4];
                ldsm4(kb, smK + np * 16 * 272 + k_off + ks * 32);
                mma16(accS[2 * np],     qa, kb);
                mma16(accS[2 * np + 1], qa, kb + 2);
            }
        }

        if (jt * 32 + 31 > it * 128 + r0) {
            #pragma unroll
            for (int nt = 0; nt < 4; nt++) {
                #pragma unroll
                for (int jj = 0; jj < 2; jj++) {
                    const int ck = jt * 32 + 8 * nt + 2 * lp + jj;
                    accS[nt][jj]     = (ck > rq0) ? -INFINITY
                                                  : accS[nt][jj] * scale;
                    accS[nt][jj + 2] = (ck > rq1) ? -INFINITY
                                                  : accS[nt][jj + 2] * scale;
                }
            }
        } else {
            #pragma unroll
            for (int nt = 0; nt < 4; nt++)
                #pragma unroll
                for (int i = 0; i < 4; i++) accS[nt][i] *= scale;
        }

        float mx0 = -INFINITY, mx1 = -INFINITY;
        #pragma unroll
        for (int nt = 0; nt < 4; nt++) {
            mx0 = fmaxf(mx0, fmaxf(accS[nt][0], accS[nt][1]));
            mx1 = fmaxf(mx1, fmaxf(accS[nt][2], accS[nt][3]));
        }
        mx0 = fmaxf(mx0, __shfl_xor_sync(0xffffffffu, mx0, 1));
        mx0 = fmaxf(mx0, __shfl_xor_sync(0xffffffffu, mx0, 2));
        mx1 = fmaxf(mx1, __shfl_xor_sync(0xffffffffu, mx1, 1));
        mx1 = fmaxf(mx1, __shfl_xor_sync(0xffffffffu, mx1, 2));
        const float mn0 = fmaxf(m0, mx0), mn1 = fmaxf(m1, mx1);
        const float al0 = __expf(m0 - mn0), al1 = __expf(m1 - mn1);
        float s0 = 0.f, s1 = 0.f;
        #pragma unroll
        for (int nt = 0; nt < 4; nt++) {
            float p;
            p = __expf(accS[nt][0] - mn0); accS[nt][0] = p; s0 += p;
            p = __expf(accS[nt][1] - mn0); accS[nt][1] = p; s0 += p;
            p = __expf(accS[nt][2] - mn1); accS[nt][2] = p; s1 += p;
            p = __expf(accS[nt][3] - mn1); accS[nt][3] = p; s1 += p;
        }
        s0 += __shfl_xor_sync(0xffffffffu, s0, 1);
        s0 += __shfl_xor_sync(0xffffffffu, s0, 2);
        s1 += __shfl_xor_sync(0xffffffffu, s1, 1);
        s1 += __shfl_xor_sync(0xffffffffu, s1, 2);
        l0 = l0 * al0 + s0; m0 = mn0;
        l1 = l1 * al1 + s1; m1 = mn1;
        #pragma unroll
        for (int nt = 0; nt < 16; nt++) {
            accO[nt][0] *= al0; accO[nt][1] *= al0;
            accO[nt][2] *= al1; accO[nt][3] *= al1;
        }

        #pragma unroll
        for (int s = 0; s < 2; s++) {
            uint32_t pa[4];
            pa[0] = packh2(accS[2 * s][0], accS[2 * s][1]);
            pa[1] = packh2(accS[2 * s][2], accS[2 * s][3]);
            pa[2] = packh2(accS[2 * s + 1][0], accS[2 * s + 1][1]);
            pa[3] = packh2(accS[2 * s + 1][2], accS[2 * s + 1][3]);
            #pragma unroll
            for (int np = 0; np < 8; np++) {
                uint32_t vb[4];
                ldsm4t(vb, smV + s * 16 * 272 + v_off + np * 32);
                mma16(accO[2 * np],     pa, vb);
                mma16(accO[2 * np + 1], pa, vb + 2);
            }
        }
    }

    const int bi = bh >> 4, h = bh & 15;
    const float inv0 = 1.0f / l0, inv1 = 1.0f / l1;
    const int row0 = it * 128 + r0 + lg;
    #pragma unroll
    for (int nt = 0; nt < 16; nt++) {
        const int d = 8 * nt + 2 * lp;
        *(uint32_t*)&g_attnh[((size_t)bi * T_ + row0) * C_ + h * 128 + d] =
            packh2(accO[nt][0] * inv0, accO[nt][1] * inv0);
        *(uint32_t*)&g_attnh[((size_t)bi * T_ + row0 + 8) * C_ + h * 128 + d] =
            packh2(accO[nt][2] * inv1, accO[nt][3] * inv1);
    }
}

// ---------------------------------------------------------------------------
// Launch
// ---------------------------------------------------------------------------
extern "C" void kernel_launch(void* const* d_in, const int* in_sizes, int n_in,
                              void* d_out, int out_size)
{
    const float* x = nullptr;
    const float* W_qkv = nullptr;
    const float* b_qkv = nullptr;
    const float* W_out = nullptr;
    const float* b_out = nullptr;
    int n4m_seen = 0;
    for (int i = 0; i < n_in; i++) {
        const int sz = in_sizes[i];
        if (sz == M_ * C_ && x == nullptr) x = (const float*)d_in[i];
        else if (sz == C_ * N1_) W_qkv = (const float*)d_in[i];
        else if (sz == N1_) b_qkv = (const float*)d_in[i];
        else if (sz == C_ * C_) {
            if (n4m_seen == 1) W_out = (const float*)d_in[i];
            n4m_seen++;
        }
        else if (sz == C_) b_out = (const float*)d_in[i];
    }
    float* out = (float*)d_out;

    void *xh, *wqkvt, *woutt, *attnh;
    cudaGetSymbolAddress(&xh, g_xh);
    cudaGetSymbolAddress(&wqkvt, g_wqkvt);
    cudaGetSymbolAddress(&woutt, g_woutt);
    cudaGetSymbolAddress(&attnh, g_attnh);

    cudaFuncSetAttribute(hgemm_kernel<0>,
                         cudaFuncAttributeMaxDynamicSharedMemorySize, GEMM_SMEM);
    cudaFuncSetAttribute(hgemm_kernel<1>,
                         cudaFuncAttributeMaxDynamicSharedMemorySize, GEMM_SMEM);
    cudaFuncSetAttribute(attn_tc_kernel,
                         cudaFuncAttributeMaxDynamicSharedMemorySize, ATTN_SMEM);

    cvt_f16_kernel<<<1184, 256>>>(x, (__half*)xh, (M_ * C_) / 4);
    transpose_f16_kernel<<<dim3(N1_ / 32, C_ / 32), 256>>>(
        W_qkv, (__half*)wqkvt, C_, N1_);
    transpose_f16_kernel<<<dim3(C_ / 32, C_ / 32), 256>>>(
        W_out, (__half*)woutt, C_, C_);

    hgemm_kernel<0><<<dim3(48, 32), 256, GEMM_SMEM>>>(
        (const __half*)xh, (const __half*)wqkvt, b_qkv, nullptr);
    attn_tc_kernel<<<dim3(16, 32), 256, ATTN_SMEM>>>();
    hgemm_kernel<1><<<dim3(16, 32), 256, GEMM_SMEM>>>(
        (const __half*)attnh, (const __half*)woutt, b_out, out);

    const size_t nbytes = (size_t)NKV * sizeof(float);
    if (out_size >= 2 * NKV)
        cudaMemcpyFromSymbolAsync(out + NKV, g_k, nbytes, 0,
                                  cudaMemcpyDeviceToDevice, 0);
    if (out_size >= 3 * NKV)
        cudaMemcpyFromSymbolAsync(out + 2 * NKV, g_v, nbytes, 0,
                                  cudaMemcpyDeviceToDevice, 0);
}

// round 7
// speedup vs baseline: 7.8689x; 1.1193x over previous
#include <cuda_runtime.h>
#include <cuda_fp16.h>
#include <math.h>
#include <stdint.h>

#define B_ 2
#define T_ 2048
#define C_ 2048
#define H_ 16
#define D_ 128
#define M_ (B_*T_)            /* 4096 */
#define N1_ (3*C_)            /* 6144 */
#define NKV (B_*H_*T_*D_)     /* 8388608 */

// Scratch (allocation-free)
__device__ __half g_xh[M_*C_];       // x  fp16
__device__ __half g_wqkvt[N1_*C_];   // W_qkv^T [n][k] fp16
__device__ __half g_woutt[C_*C_];    // W_out^T [n][k] fp16
__device__ __half g_qh[NKV];
__device__ __half g_kh[NKV];
__device__ __half g_vh[NKV];
__device__ float  g_k[NKV];          // fp32 k (output fidelity)
__device__ float  g_v[NKV];          // fp32 v
__device__ __half g_attnh[M_*C_];    // attention out fp16

// ---------------------------------------------------------------------------
// Helpers
// ---------------------------------------------------------------------------
__device__ __forceinline__ uint32_t smem_u32(const void* p) {
    uint32_t a;
    asm("{ .reg .u64 t; cvta.to.shared.u64 t, %1; cvt.u32.u64 %0, t; }"
        : "=r"(a) : "l"(p));
    return a;
}
__device__ __forceinline__ void cpasync16(uint32_t dst, const void* src) {
    asm volatile("cp.async.cg.shared.global [%0], [%1], 16;"
                 :: "r"(dst), "l"(src) : "memory");
}
#define CP_COMMIT() asm volatile("cp.async.commit_group;" ::: "memory")
__device__ __forceinline__ void ldsm4(uint32_t* r, uint32_t a) {
    asm volatile("ldmatrix.sync.aligned.m8n8.x4.shared.b16 {%0,%1,%2,%3}, [%4];"
                 : "=r"(r[0]), "=r"(r[1]), "=r"(r[2]), "=r"(r[3]) : "r"(a));
}
__device__ __forceinline__ void ldsm4t(uint32_t* r, uint32_t a) {
    asm volatile("ldmatrix.sync.aligned.m8n8.x4.trans.shared.b16 {%0,%1,%2,%3}, [%4];"
                 : "=r"(r[0]), "=r"(r[1]), "=r"(r[2]), "=r"(r[3]) : "r"(a));
}
__device__ __forceinline__ void mma16(float* d, const uint32_t* a,
                                      const uint32_t* b) {
    asm volatile(
        "mma.sync.aligned.m16n8k16.row.col.f32.f16.f16.f32 "
        "{%0,%1,%2,%3}, {%4,%5,%6,%7}, {%8,%9}, {%0,%1,%2,%3};"
        : "+f"(d[0]), "+f"(d[1]), "+f"(d[2]), "+f"(d[3])
        : "r"(a[0]), "r"(a[1]), "r"(a[2]), "r"(a[3]), "r"(b[0]), "r"(b[1]));
}
__device__ __forceinline__ uint32_t packh2(float lo, float hi) {
    __half2 h = __floats2half2_rn(lo, hi);
    return *(uint32_t*)&h;
}

// ---------------------------------------------------------------------------
// Prep kernels
// ---------------------------------------------------------------------------
__global__ void cvt_f16_kernel(const float* __restrict__ src,
                               __half* __restrict__ dst, int n4)
{
    for (int i = blockIdx.x * blockDim.x + threadIdx.x; i < n4;
         i += gridDim.x * blockDim.x) {
        float4 v = __ldg((const float4*)src + i);
        uint2 o;
        o.x = packh2(v.x, v.y);
        o.y = packh2(v.z, v.w);
        ((uint2*)dst)[i] = o;
    }
}

__global__ void __launch_bounds__(256) transpose_f16_kernel(
    const float* __restrict__ W, __half* __restrict__ Wt, int K, int N)
{
    __shared__ float tile[32][33];
    const int k0 = blockIdx.y << 5, n0 = blockIdx.x << 5;
    const int tx = threadIdx.x & 31, ty = threadIdx.x >> 5;
    #pragma unroll
    for (int r = 0; r < 4; r++)
        tile[ty + 8 * r][tx] = __ldg(W + (size_t)(k0 + ty + 8 * r) * N + n0 + tx);
    __syncthreads();
    #pragma unroll
    for (int r = 0; r < 4; r++)
        Wt[(size_t)(n0 + ty + 8 * r) * K + k0 + tx] =
            __float2half_rn(tile[tx][ty + 8 * r]);
}

// ---------------------------------------------------------------------------
// fp16 mma.sync GEMM: C[4096,N] = A @ Wt^T + bias. CTA 128x128, BK=32,
// 4 warps (2m x 2n), warp tile 64x64 -> 1.5x higher FLOP/LDSM-byte.
// 5-stage cp.async, __syncthreads every 2 iters. Row stride 80B.
// ---------------------------------------------------------------------------
#define GSTG 20480
#define GEMM_SMEM (5 * GSTG)

template <int MODE>
__global__ void __launch_bounds__(128, 2) hgemm_kernel(
    const __half* __restrict__ Ag, const __half* __restrict__ Bt,
    const float* __restrict__ bias, float* __restrict__ Cout)
{
    extern __shared__ char dynsm[];
    const uint32_t smb = smem_u32(dynsm);
    const int tid  = threadIdx.x;
    const int lane = tid & 31;
    const int warp = tid >> 5;
    const int wm = warp & 1, wn = warp >> 1;
    const int bm = blockIdx.y << 7, bn = blockIdx.x << 7;
    const int lg = lane >> 2, lp = lane & 3;

    float acc[4][8][4];
    #pragma unroll
    for (int mt = 0; mt < 4; mt++)
        #pragma unroll
        for (int nt = 0; nt < 8; nt++)
            #pragma unroll
            for (int i = 0; i < 4; i++) acc[mt][nt][i] = 0.f;

    const int l_row = tid >> 2;          // 0..31
    const int l_seg = tid & 3;           // 16B segment
    auto load_tiles = [&](int it, int s) {
        const uint32_t base = smb + s * GSTG;
        #pragma unroll
        for (int j = 0; j < 4; j++) {
            const int row = l_row + 32 * j;
            cpasync16(base + row * 80 + l_seg * 16,
                      Ag + (size_t)(bm + row) * 2048 + it * 32 + l_seg * 8);
            cpasync16(base + 10240 + row * 80 + l_seg * 16,
                      Bt + (size_t)(bn + row) * 2048 + it * 32 + l_seg * 8);
        }
        CP_COMMIT();
    };

    const uint32_t a_off = (lane & 15) * 80 + (lane >> 4) * 16;
    const uint32_t b_off = ((lane & 7) + ((lane >> 4) & 1) * 8) * 80
                           + ((lane >> 3) & 1) * 16;

    auto compute_stage = [&](int s) {
        const uint32_t smA = smb + s * GSTG + wm * 64 * 80 + a_off;
        const uint32_t smB = smb + s * GSTG + 10240 + wn * 64 * 80 + b_off;
        #pragma unroll
        for (int ks = 0; ks < 2; ks++) {
            uint32_t a[4][4], b[4][4];
            #pragma unroll
            for (int mt = 0; mt < 4; mt++)
                ldsm4(a[mt], smA + mt * 16 * 80 + ks * 32);
            #pragma unroll
            for (int np = 0; np < 4; np++)
                ldsm4(b[np], smB + np * 16 * 80 + ks * 32);
            #pragma unroll
            for (int mt = 0; mt < 4; mt++)
                #pragma unroll
                for (int np = 0; np < 4; np++) {
                    mma16(acc[mt][2 * np],     a[mt], b[np]);
                    mma16(acc[mt][2 * np + 1], a[mt], b[np] + 2);
                }
        }
    };

    const int NIT = 2048 / 32;  // 64
    load_tiles(0, 0);
    load_tiles(1, 1);
    load_tiles(2, 2);

    #pragma unroll 1
    for (int t = 0; t < NIT / 2; t++) {
        const int it = 2 * t;
        if (t == NIT / 2 - 1)
            asm volatile("cp.async.wait_group 0;" ::: "memory");
        else
            asm volatile("cp.async.wait_group 1;" ::: "memory");
        __syncthreads();
        if (it + 3 < NIT) load_tiles(it + 3, (it + 3) % 5);
        if (it + 4 < NIT) load_tiles(it + 4, (it + 4) % 5);
        compute_stage(it % 5);
        compute_stage((it + 1) % 5);
    }

    // Epilogue
    #pragma unroll
    for (int mt = 0; mt < 4; mt++) {
        #pragma unroll
        for (int half = 0; half < 2; half++) {
            const int m = bm + wm * 64 + mt * 16 + lg + half * 8;
            #pragma unroll
            for (int nt = 0; nt < 8; nt++) {
                const int n = bn + wn * 64 + nt * 8 + 2 * lp;
                float2 bv = *(const float2*)(bias + n);
                const float o0 = acc[mt][nt][half * 2 + 0] + bv.x;
                const float o1 = acc[mt][nt][half * 2 + 1] + bv.y;
                if (MODE == 0) {
                    const int which = n >> 11;
                    const int h = (n & 2047) >> 7;
                    const int d = n & 127;
                    const int bi = m >> 11, t2 = m & 2047;
                    const size_t idx = (((size_t)bi * H_ + h) * T_ + t2) * D_ + d;
                    const uint32_t p = packh2(o0, o1);
                    if (which == 0) {
                        *(uint32_t*)&g_qh[idx] = p;
                    } else if (which == 1) {
                        *(uint32_t*)&g_kh[idx] = p;
                        *(float2*)&g_k[idx] = make_float2(o0, o1);
                    } else {
                        *(uint32_t*)&g_vh[idx] = p;
                        *(float2*)&g_v[idx] = make_float2(o0, o1);
                    }
                } else {
                    *(float2*)(Cout + (size_t)m * 2048 + n) = make_float2(o0, o1);
                }
            }
        }
    }
}

// ---------------------------------------------------------------------------
// fp16 flash attention, causal. Br=128 (8 warps x 16 rows), Bc=32, D=128.
// (unchanged from round 6 best)
// ---------------------------------------------------------------------------
#define AQ_BYTES (128 * 272)
#define AKV_BYTES (32 * 272)
#define ATTN_SMEM (AQ_BYTES + 4 * AKV_BYTES)

__global__ void __launch_bounds__(256, 2) attn_tc_kernel()
{
    extern __shared__ char dynsm[];
    const uint32_t smb = smem_u32(dynsm);
    const uint32_t smQ = smb;

    const int it  = (gridDim.x - 1) - blockIdx.x;
    const int bh  = blockIdx.y;
    const int tid = threadIdx.x;
    const int lane = tid & 31;
    const int w   = tid >> 5;
    const int lg = lane >> 2, lp = lane & 3;
    const int r0 = w * 16;

    const __half* Qg = g_qh + (size_t)bh * (T_ * D_);
    const __half* Kg = g_kh + (size_t)bh * (T_ * D_);
    const __half* Vg = g_vh + (size_t)bh * (T_ * D_);

    {
        const int row = tid >> 1;
        const int s0 = (tid & 1) * 8;
        #pragma unroll
        for (int j = 0; j < 8; j++)
            cpasync16(smQ + row * 272 + (s0 + j) * 16,
                      Qg + (size_t)(it * 128 + row) * 128 + (s0 + j) * 8);
    }
    const int kv_row = tid >> 3;
    const int kv_s0 = (tid & 7) * 2;
    auto load_kv = [&](int jt, int st) {
        const uint32_t smK = smb + AQ_BYTES + st * AKV_BYTES;
        const uint32_t smV = smb + AQ_BYTES + 2 * AKV_BYTES + st * AKV_BYTES;
        #pragma unroll
        for (int j = 0; j < 2; j++) {
            const int seg = kv_s0 + j;
            cpasync16(smK + kv_row * 272 + seg * 16,
                      Kg + (size_t)(jt * 32 + kv_row) * 128 + seg * 8);
            cpasync16(smV + kv_row * 272 + seg * 16,
                      Vg + (size_t)(jt * 32 + kv_row) * 128 + seg * 8);
        }
        CP_COMMIT();
    };
    load_kv(0, 0);

    const uint32_t q_off = (r0 + (lane & 15)) * 272 + (lane >> 4) * 16;
    const uint32_t k_off = ((lane & 7) + ((lane >> 4) & 1) * 8) * 272
                           + ((lane >> 3) & 1) * 16;
    const uint32_t v_off = ((lane & 7) + ((lane >> 3) & 1) * 8) * 272
                           + (lane >> 4) * 16;

    float accO[16][4];
    #pragma unroll
    for (int nt = 0; nt < 16; nt++)
        #pragma unroll
        for (int i = 0; i < 4; i++) accO[nt][i] = 0.f;
    float m0 = -INFINITY, m1 = -INFINITY, l0 = 0.f, l1 = 0.f;
    const float scale = 0.08838834764831845f;
    const int jmax = 4 * it + 3;
    const int rq0 = it * 128 + r0 + lg;
    const int rq1 = rq0 + 8;

    for (int jt = 0; jt <= jmax; jt++) {
        const int cur = jt & 1;
        asm volatile("cp.async.wait_group 0;" ::: "memory");
        __syncthreads();
        if (jt < jmax) load_kv(jt + 1, cur ^ 1);

        if (jt * 32 > it * 128 + r0 + 15) continue;

        const uint32_t smK = smb + AQ_BYTES + cur * AKV_BYTES;
        const uint32_t smV = smb + AQ_BYTES + 2 * AKV_BYTES + cur * AKV_BYTES;

        float accS[4][4];
        #pragma unroll
        for (int nt = 0; nt < 4; nt++)
            #pragma unroll
            for (int i = 0; i < 4; i++) accS[nt][i] = 0.f;
        #pragma unroll
        for (int ks = 0; ks < 8; ks++) {
            uint32_t qa[4];
            ldsm4(qa, smQ + q_off + ks * 32);
            #pragma unroll
            for (int np = 0; np < 2; np++) {
                uint32_t kb[4];
                ldsm4(kb, smK + np * 16 * 272 + k_off + ks * 32);
                mma16(accS[2 * np],     qa, kb);
                mma16(accS[2 * np + 1], qa, kb + 2);
            }
        }

        if (jt * 32 + 31 > it * 128 + r0) {
            #pragma unroll
            for (int nt = 0; nt < 4; nt++) {
                #pragma unroll
                for (int jj = 0; jj < 2; jj++) {
                    const int ck = jt * 32 + 8 * nt + 2 * lp + jj;
                    accS[nt][jj]     = (ck > rq0) ? -INFINITY
                                                  : accS[nt][jj] * scale;
                    accS[nt][jj + 2] = (ck > rq1) ? -INFINITY
                                                  : accS[nt][jj + 2] * scale;
                }
            }
        } else {
            #pragma unroll
            for (int nt = 0; nt < 4; nt++)
                #pragma unroll
                for (int i = 0; i < 4; i++) accS[nt][i] *= scale;
        }

        float mx0 = -INFINITY, mx1 = -INFINITY;
        #pragma unroll
        for (int nt = 0; nt < 4; nt++) {
            mx0 = fmaxf(mx0, fmaxf(accS[nt][0], accS[nt][1]));
            mx1 = fmaxf(mx1, fmaxf(accS[nt][2], accS[nt][3]));
        }
        mx0 = fmaxf(mx0, __shfl_xor_sync(0xffffffffu, mx0, 1));
        mx0 = fmaxf(mx0, __shfl_xor_sync(0xffffffffu, mx0, 2));
        mx1 = fmaxf(mx1, __shfl_xor_sync(0xffffffffu, mx1, 1));
        mx1 = fmaxf(mx1, __shfl_xor_sync(0xffffffffu, mx1, 2));
        const float mn0 = fmaxf(m0, mx0), mn1 = fmaxf(m1, mx1);
        const float al0 = __expf(m0 - mn0), al1 = __expf(m1 - mn1);
        float s0 = 0.f, s1 = 0.f;
        #pragma unroll
        for (int nt = 0; nt < 4; nt++) {
            float p;
            p = __expf(accS[nt][0] - mn0); accS[nt][0] = p; s0 += p;
            p = __expf(accS[nt][1] - mn0); accS[nt][1] = p; s0 += p;
            p = __expf(accS[nt][2] - mn1); accS[nt][2] = p; s1 += p;
            p = __expf(accS[nt][3] - mn1); accS[nt][3] = p; s1 += p;
        }
        s0 += __shfl_xor_sync(0xffffffffu, s0, 1);
        s0 += __shfl_xor_sync(0xffffffffu, s0, 2);
        s1 += __shfl_xor_sync(0xffffffffu, s1, 1);
        s1 += __shfl_xor_sync(0xffffffffu, s1, 2);
        l0 = l0 * al0 + s0; m0 = mn0;
        l1 = l1 * al1 + s1; m1 = mn1;
        #pragma unroll
        for (int nt = 0; nt < 16; nt++) {
            accO[nt][0] *= al0; accO[nt][1] *= al0;
            accO[nt][2] *= al1; accO[nt][3] *= al1;
        }

        #pragma unroll
        for (int s = 0; s < 2; s++) {
            uint32_t pa[4];
            pa[0] = packh2(accS[2 * s][0], accS[2 * s][1]);
            pa[1] = packh2(accS[2 * s][2], accS[2 * s][3]);
            pa[2] = packh2(accS[2 * s + 1][0], accS[2 * s + 1][1]);
            pa[3] = packh2(accS[2 * s + 1][2], accS[2 * s + 1][3]);
            #pragma unroll
            for (int np = 0; np < 8; np++) {
                uint32_t vb[4];
                ldsm4t(vb, smV + s * 16 * 272 + v_off + np * 32);
                mma16(accO[2 * np],     pa, vb);
                mma16(accO[2 * np + 1], pa, vb + 2);
            }
        }
    }

    const int bi = bh >> 4, h = bh & 15;
    const float inv0 = 1.0f / l0, inv1 = 1.0f / l1;
    const int row0 = it * 128 + r0 + lg;
    #pragma unroll
    for (int nt = 0; nt < 16; nt++) {
        const int d = 8 * nt + 2 * lp;
        *(uint32_t*)&g_attnh[((size_t)bi * T_ + row0) * C_ + h * 128 + d] =
            packh2(accO[nt][0] * inv0, accO[nt][1] * inv0);
        *(uint32_t*)&g_attnh[((size_t)bi * T_ + row0 + 8) * C_ + h * 128 + d] =
            packh2(accO[nt][2] * inv1, accO[nt][3] * inv1);
    }
}

// ---------------------------------------------------------------------------
// Launch
// ---------------------------------------------------------------------------
extern "C" void kernel_launch(void* const* d_in, const int* in_sizes, int n_in,
                              void* d_out, int out_size)
{
    const float* x = nullptr;
    const float* W_qkv = nullptr;
    const float* b_qkv = nullptr;
    const float* W_out = nullptr;
    const float* b_out = nullptr;
    int n4m_seen = 0;
    for (int i = 0; i < n_in; i++) {
        const int sz = in_sizes[i];
        if (sz == M_ * C_ && x == nullptr) x = (const float*)d_in[i];
        else if (sz == C_ * N1_) W_qkv = (const float*)d_in[i];
        else if (sz == N1_) b_qkv = (const float*)d_in[i];
        else if (sz == C_ * C_) {
            if (n4m_seen == 1) W_out = (const float*)d_in[i];
            n4m_seen++;
        }
        else if (sz == C_) b_out = (const float*)d_in[i];
    }
    float* out = (float*)d_out;

    void *xh, *wqkvt, *woutt, *attnh;
    cudaGetSymbolAddress(&xh, g_xh);
    cudaGetSymbolAddress(&wqkvt, g_wqkvt);
    cudaGetSymbolAddress(&woutt, g_woutt);
    cudaGetSymbolAddress(&attnh, g_attnh);

    cudaFuncSetAttribute(hgemm_kernel<0>,
                         cudaFuncAttributeMaxDynamicSharedMemorySize, GEMM_SMEM);
    cudaFuncSetAttribute(hgemm_kernel<1>,
                         cudaFuncAttributeMaxDynamicSharedMemorySize, GEMM_SMEM);
    cudaFuncSetAttribute(attn_tc_kernel,
                         cudaFuncAttributeMaxDynamicSharedMemorySize, ATTN_SMEM);

    cvt_f16_kernel<<<1184, 256>>>(x, (__half*)xh, (M_ * C_) / 4);
    transpose_f16_kernel<<<dim3(N1_ / 32, C_ / 32), 256>>>(
        W_qkv, (__half*)wqkvt, C_, N1_);
    transpose_f16_kernel<<<dim3(C_ / 32, C_ / 32), 256>>>(
        W_out, (__half*)woutt, C_, C_);

    hgemm_kernel<0><<<dim3(48, 32), 128, GEMM_SMEM>>>(
        (const __half*)xh, (const __half*)wqkvt, b_qkv, nullptr);
    attn_tc_kernel<<<dim3(16, 32), 256, ATTN_SMEM>>>();
    hgemm_kernel<1><<<dim3(16, 32), 128, GEMM_SMEM>>>(
        (const __half*)attnh, (const __half*)woutt, b_out, out);

    const size_t nbytes = (size_t)NKV * sizeof(float);
    if (out_size >= 2 * NKV)
        cudaMemcpyFromSymbolAsync(out + NKV, g_k, nbytes, 0,
                                  cudaMemcpyDeviceToDevice, 0);
    if (out_size >= 3 * NKV)
        cudaMemcpyFromSymbolAsync(out + 2 * NKV, g_v, nbytes, 0,
                                  cudaMemcpyDeviceToDevice, 0);
}

// round 9
// speedup vs baseline: 8.0840x; 1.0273x over previous
#include <cuda_runtime.h>
#include <cuda_fp16.h>
#include <math.h>
#include <stdint.h>

#define B_ 2
#define T_ 2048
#define C_ 2048
#define H_ 16
#define D_ 128
#define M_ (B_*T_)            /* 4096 */
#define N1_ (3*C_)            /* 6144 */
#define NKV (B_*H_*T_*D_)     /* 8388608 */

// Scratch (allocation-free)
__device__ __half g_xh[M_*C_];       // x  fp16
__device__ __half g_wqkvt[N1_*C_];   // W_qkv^T [n][k] fp16
__device__ __half g_woutt[C_*C_];    // W_out^T [n][k] fp16
__device__ __half g_qh[NKV];
__device__ __half g_kh[NKV];
__device__ __half g_vh[NKV];
__device__ float  g_k[NKV];          // fp32 k fallback
__device__ float  g_v[NKV];          // fp32 v fallback
__device__ __half g_attnh[M_*C_];    // attention out fp16

// ---------------------------------------------------------------------------
// Helpers
// ---------------------------------------------------------------------------
__device__ __forceinline__ uint32_t smem_u32(const void* p) {
    uint32_t a;
    asm("{ .reg .u64 t; cvta.to.shared.u64 t, %1; cvt.u32.u64 %0, t; }"
        : "=r"(a) : "l"(p));
    return a;
}
__device__ __forceinline__ void cpasync16(uint32_t dst, const void* src) {
    asm volatile("cp.async.cg.shared.global [%0], [%1], 16;"
                 :: "r"(dst), "l"(src) : "memory");
}
#define CP_COMMIT() asm volatile("cp.async.commit_group;" ::: "memory")
__device__ __forceinline__ void ldsm4(uint32_t* r, uint32_t a) {
    asm volatile("ldmatrix.sync.aligned.m8n8.x4.shared.b16 {%0,%1,%2,%3}, [%4];"
                 : "=r"(r[0]), "=r"(r[1]), "=r"(r[2]), "=r"(r[3]) : "r"(a));
}
__device__ __forceinline__ void ldsm4t(uint32_t* r, uint32_t a) {
    asm volatile("ldmatrix.sync.aligned.m8n8.x4.trans.shared.b16 {%0,%1,%2,%3}, [%4];"
                 : "=r"(r[0]), "=r"(r[1]), "=r"(r[2]), "=r"(r[3]) : "r"(a));
}
__device__ __forceinline__ void mma16(float* d, const uint32_t* a,
                                      const uint32_t* b) {
    asm volatile(
        "mma.sync.aligned.m16n8k16.row.col.f32.f16.f16.f32 "
        "{%0,%1,%2,%3}, {%4,%5,%6,%7}, {%8,%9}, {%0,%1,%2,%3};"
        : "+f"(d[0]), "+f"(d[1]), "+f"(d[2]), "+f"(d[3])
        : "r"(a[0]), "r"(a[1]), "r"(a[2]), "r"(a[3]), "r"(b[0]), "r"(b[1]));
}
__device__ __forceinline__ uint32_t packh2(float lo, float hi) {
    __half2 h = __floats2half2_rn(lo, hi);
    return *(uint32_t*)&h;
}

// ---------------------------------------------------------------------------
// Fused prep: cvt x->f16, transpose+cvt W_qkv and W_out (one launch)
// Block ranges: [0, 12288) wqkv transpose; [12288, 16384) wout transpose;
// [16384, 17408) x conversion (grid-stride).
// ---------------------------------------------------------------------------
__device__ __forceinline__ void transpose_body(
    const float* __restrict__ W, __half* __restrict__ Wt, int K, int N,
    int bx, int by, float (*tile)[33])
{
    const int k0 = by << 5, n0 = bx << 5;
    const int tx = threadIdx.x & 31, ty = threadIdx.x >> 5;
    #pragma unroll
    for (int r = 0; r < 4; r++)
        tile[ty + 8 * r][tx] = __ldg(W + (size_t)(k0 + ty + 8 * r) * N + n0 + tx);
    __syncthreads();
    #pragma unroll
    for (int r = 0; r < 4; r++)
        Wt[(size_t)(n0 + ty + 8 * r) * K + k0 + tx] =
            __float2half_rn(tile[tx][ty + 8 * r]);
}

__global__ void __launch_bounds__(256) prep_kernel(
    const float* __restrict__ x,
    const float* __restrict__ Wqkv,
    const float* __restrict__ Wout)
{
    __shared__ float tile[32][33];
    const int bid = blockIdx.x;
    if (bid < 12288) {
        transpose_body(Wqkv, g_wqkvt, C_, N1_, bid % 192, bid / 192, tile);
    } else if (bid < 16384) {
        const int r = bid - 12288;
        transpose_body(Wout, g_woutt, C_, C_, r & 63, r >> 6, tile);
    } else {
        const int n4 = (M_ * C_) / 4;
        for (int i = (bid - 16384) * 256 + threadIdx.x; i < n4; i += 1024 * 256) {
            float4 v = __ldg((const float4*)x + i);
            uint2 o;
            o.x = packh2(v.x, v.y);
            o.y = packh2(v.z, v.w);
            ((uint2*)g_xh)[i] = o;
        }
    }
}

// ---------------------------------------------------------------------------
// fp16 mma.sync GEMM: C[4096,N] = A @ Wt^T + bias. CTA 128x128, BK=32,
// 4 warps (2m x 2n), warp tile 64x64. 3-stage cp.async, barrier/iter,
// 3 CTAs/SM (12 warps/SM = 3/SMSP). Row stride 80B (conflict-free).
// ---------------------------------------------------------------------------
#define GSTG 20480
#define GEMM_SMEM (3 * GSTG)

template <int MODE>
__global__ void __launch_bounds__(128, 3) hgemm_kernel(
    const __half* __restrict__ Ag, const __half* __restrict__ Bt,
    const float* __restrict__ bias, float* __restrict__ Cout,
    float* __restrict__ Kout, float* __restrict__ Vout)
{
    extern __shared__ char dynsm[];
    const uint32_t smb = smem_u32(dynsm);
    const int tid  = threadIdx.x;
    const int lane = tid & 31;
    const int warp = tid >> 5;
    const int wm = warp & 1, wn = warp >> 1;
    const int bm = blockIdx.y << 7, bn = blockIdx.x << 7;
    const int lg = lane >> 2, lp = lane & 3;

    float acc[4][8][4];
    #pragma unroll
    for (int mt = 0; mt < 4; mt++)
        #pragma unroll
        for (int nt = 0; nt < 8; nt++)
            #pragma unroll
            for (int i = 0; i < 4; i++) acc[mt][nt][i] = 0.f;

    const int l_row = tid >> 2;
    const int l_seg = tid & 3;
    auto load_tiles = [&](int it, int s) {
        const uint32_t base = smb + s * GSTG;
        #pragma unroll
        for (int j = 0; j < 4; j++) {
            const int row = l_row + 32 * j;
            cpasync16(base + row * 80 + l_seg * 16,
                      Ag + (size_t)(bm + row) * 2048 + it * 32 + l_seg * 8);
            cpasync16(base + 10240 + row * 80 + l_seg * 16,
                      Bt + (size_t)(bn + row) * 2048 + it * 32 + l_seg * 8);
        }
        CP_COMMIT();
    };

    const uint32_t a_off = (lane & 15) * 80 + (lane >> 4) * 16;
    const uint32_t b_off = ((lane & 7) + ((lane >> 4) & 1) * 8) * 80
                           + ((lane >> 3) & 1) * 16;

    auto compute_stage = [&](int s) {
        const uint32_t smA = smb + s * GSTG + wm * 64 * 80 + a_off;
        const uint32_t smB = smb + s * GSTG + 10240 + wn * 64 * 80 + b_off;
        #pragma unroll
        for (int ks = 0; ks < 2; ks++) {
            uint32_t a[4][4], b[4][4];
            #pragma unroll
            for (int mt = 0; mt < 4; mt++)
                ldsm4(a[mt], smA + mt * 16 * 80 + ks * 32);
            #pragma unroll
            for (int np = 0; np < 4; np++)
                ldsm4(b[np], smB + np * 16 * 80 + ks * 32);
            #pragma unroll
            for (int mt = 0; mt < 4; mt++)
                #pragma unroll
                for (int np = 0; np < 4; np++) {
                    mma16(acc[mt][2 * np],     a[mt], b[np]);
                    mma16(acc[mt][2 * np + 1], a[mt], b[np] + 2);
                }
        }
    };

    const int NIT = 2048 / 32;  // 64
    load_tiles(0, 0);
    load_tiles(1, 1);

    #pragma unroll 1
    for (int it = 0; it < NIT; it++) {
        if (it + 2 < NIT)
            asm volatile("cp.async.wait_group 1;" ::: "memory");
        else
            asm volatile("cp.async.wait_group 0;" ::: "memory");
        __syncthreads();
        if (it + 2 < NIT) load_tiles(it + 2, (it + 2) % 3);
        compute_stage(it % 3);
    }

    // Epilogue
    #pragma unroll
    for (int mt = 0; mt < 4; mt++) {
        #pragma unroll
        for (int half = 0; half < 2; half++) {
            const int m = bm + wm * 64 + mt * 16 + lg + half * 8;
            #pragma unroll
            for (int nt = 0; nt < 8; nt++) {
                const int n = bn + wn * 64 + nt * 8 + 2 * lp;
                float2 bv = *(const float2*)(bias + n);
                const float o0 = acc[mt][nt][half * 2 + 0] + bv.x;
                const float o1 = acc[mt][nt][half * 2 + 1] + bv.y;
                if (MODE == 0) {
                    const int which = n >> 11;
                    const int h = (n & 2047) >> 7;
                    const int d = n & 127;
                    const int bi = m >> 11, t2 = m & 2047;
                    const size_t idx = (((size_t)bi * H_ + h) * T_ + t2) * D_ + d;
                    const uint32_t p = packh2(o0, o1);
                    if (which == 0) {
                        *(uint32_t*)&g_qh[idx] = p;
                    } else if (which == 1) {
                        *(uint32_t*)&g_kh[idx] = p;
                        *(float2*)&Kout[idx] = make_float2(o0, o1);
                    } else {
                        *(uint32_t*)&g_vh[idx] = p;
                        *(float2*)&Vout[idx] = make_float2(o0, o1);
                    }
                } else {
                    *(float2*)(Cout + (size_t)m * 2048 + n) = make_float2(o0, o1);
                }
            }
        }
    }
}

// ---------------------------------------------------------------------------
// fp16 flash attention, causal. Br=128 (8 warps x 16 rows), Bc=32, D=128.
// ---------------------------------------------------------------------------
#define AQ_BYTES (128 * 272)
#define AKV_BYTES (32 * 272)
#define ATTN_SMEM (AQ_BYTES + 4 * AKV_BYTES)

__global__ void __launch_bounds__(256, 2) attn_tc_kernel()
{
    extern __shared__ char dynsm[];
    const uint32_t smb = smem_u32(dynsm);
    const uint32_t smQ = smb;

    const int it  = (gridDim.x - 1) - blockIdx.x;
    const int bh  = blockIdx.y;
    const int tid = threadIdx.x;
    const int lane = tid & 31;
    const int w   = tid >> 5;
    const int lg = lane >> 2, lp = lane & 3;
    const int r0 = w * 16;

    const __half* Qg = g_qh + (size_t)bh * (T_ * D_);
    const __half* Kg = g_kh + (size_t)bh * (T_ * D_);
    const __half* Vg = g_vh + (size_t)bh * (T_ * D_);

    {
        const int row = tid >> 1;
        const int s0 = (tid & 1) * 8;
        #pragma unroll
        for (int j = 0; j < 8; j++)
            cpasync16(smQ + row * 272 + (s0 + j) * 16,
                      Qg + (size_t)(it * 128 + row) * 128 + (s0 + j) * 8);
    }
    const int kv_row = tid >> 3;
    const int kv_s0 = (tid & 7) * 2;
    auto load_kv = [&](int jt, int st) {
        const uint32_t smK = smb + AQ_BYTES + st * AKV_BYTES;
        const uint32_t smV = smb + AQ_BYTES + 2 * AKV_BYTES + st * AKV_BYTES;
        #pragma unroll
        for (int j = 0; j < 2; j++) {
            const int seg = kv_s0 + j;
            cpasync16(smK + kv_row * 272 + seg * 16,
                      Kg + (size_t)(jt * 32 + kv_row) * 128 + seg * 8);
            cpasync16(smV + kv_row * 272 + seg * 16,
                      Vg + (size_t)(jt * 32 + kv_row) * 128 + seg * 8);
        }
        CP_COMMIT();
    };
    load_kv(0, 0);

    const uint32_t q_off = (r0 + (lane & 15)) * 272 + (lane >> 4) * 16;
    const uint32_t k_off = ((lane & 7) + ((lane >> 4) & 1) * 8) * 272
                           + ((lane >> 3) & 1) * 16;
    const uint32_t v_off = ((lane & 7) + ((lane >> 3) & 1) * 8) * 272
                           + (lane >> 4) * 16;

    float accO[16][4];
    #pragma unroll
    for (int nt = 0; nt < 16; nt++)
        #pragma unroll
        for (int i = 0; i < 4; i++) accO[nt][i] = 0.f;
    float m0 = -INFINITY, m1 = -INFINITY, l0 = 0.f, l1 = 0.f;
    const float scale = 0.08838834764831845f;
    const int jmax = 4 * it + 3;
    const int rq0 = it * 128 + r0 + lg;
    const int rq1 = rq0 + 8;

    for (int jt = 0; jt <= jmax; jt++) {
        const int cur = jt & 1;
        asm volatile("cp.async.wait_group 0;" ::: "memory");
        __syncthreads();
        if (jt < jmax) load_kv(jt + 1, cur ^ 1);

        if (jt * 32 > it * 128 + r0 + 15) continue;

        const uint32_t smK = smb + AQ_BYTES + cur * AKV_BYTES;
        const uint32_t smV = smb + AQ_BYTES + 2 * AKV_BYTES + cur * AKV_BYTES;

        float accS[4][4];
        #pragma unroll
        for (int nt = 0; nt < 4; nt++)
            #pragma unroll
            for (int i = 0; i < 4; i++) accS[nt][i] = 0.f;
        #pragma unroll
        for (int ks = 0; ks < 8; ks++) {
            uint32_t qa[4];
            ldsm4(qa, smQ + q_off + ks * 32);
            #pragma unroll
            for (int np = 0; np < 2; np++) {
                uint32_t kb[4];
                ldsm4(kb, smK + np * 16 * 272 + k_off + ks * 32);
                mma16(accS[2 * np],     qa, kb);
                mma16(accS[2 * np + 1], qa, kb + 2);
            }
        }

        if (jt * 32 + 31 > it * 128 + r0) {
            #pragma unroll
            for (int nt = 0; nt < 4; nt++) {
                #pragma unroll
                for (int jj = 0; jj < 2; jj++) {
                    const int ck = jt * 32 + 8 * nt + 2 * lp + jj;
                    accS[nt][jj]     = (ck > rq0) ? -INFINITY
                                                  : accS[nt][jj] * scale;
                    accS[nt][jj + 2] = (ck > rq1) ? -INFINITY
                                                  : accS[nt][jj + 2] * scale;
                }
            }
        } else {
            #pragma unroll
            for (int nt = 0; nt < 4; nt++)
                #pragma unroll
                for (int i = 0; i < 4; i++) accS[nt][i] *= scale;
        }

        float mx0 = -INFINITY, mx1 = -INFINITY;
        #pragma unroll
        for (int nt = 0; nt < 4; nt++) {
            mx0 = fmaxf(mx0, fmaxf(accS[nt][0], accS[nt][1]));
            mx1 = fmaxf(mx1, fmaxf(accS[nt][2], accS[nt][3]));
        }
        mx0 = fmaxf(mx0, __shfl_xor_sync(0xffffffffu, mx0, 1));
        mx0 = fmaxf(mx0, __shfl_xor_sync(0xffffffffu, mx0, 2));
        mx1 = fmaxf(mx1, __shfl_xor_sync(0xffffffffu, mx1, 1));
        mx1 = fmaxf(mx1, __shfl_xor_sync(0xffffffffu, mx1, 2));
        const float mn0 = fmaxf(m0, mx0), mn1 = fmaxf(m1, mx1);
        const float al0 = __expf(m0 - mn0), al1 = __expf(m1 - mn1);
        float s0 = 0.f, s1 = 0.f;
        #pragma unroll
        for (int nt = 0; nt < 4; nt++) {
            float p;
            p = __expf(accS[nt][0] - mn0); accS[nt][0] = p; s0 += p;
            p = __expf(accS[nt][1] - mn0); accS[nt][1] = p; s0 += p;
            p = __expf(accS[nt][2] - mn1); accS[nt][2] = p; s1 += p;
            p = __expf(accS[nt][3] - mn1); accS[nt][3] = p; s1 += p;
        }
        s0 += __shfl_xor_sync(0xffffffffu, s0, 1);
        s0 += __shfl_xor_sync(0xffffffffu, s0, 2);
        s1 += __shfl_xor_sync(0xffffffffu, s1, 1);
        s1 += __shfl_xor_sync(0xffffffffu, s1, 2);
        l0 = l0 * al0 + s0; m0 = mn0;
        l1 = l1 * al1 + s1; m1 = mn1;
        #pragma unroll
        for (int nt = 0; nt < 16; nt++) {
            accO[nt][0] *= al0; accO[nt][1] *= al0;
            accO[nt][2] *= al1; accO[nt][3] *= al1;
        }

        #pragma unroll
        for (int s = 0; s < 2; s++) {
            uint32_t pa[4];
            pa[0] = packh2(accS[2 * s][0], accS[2 * s][1]);
            pa[1] = packh2(accS[2 * s][2], accS[2 * s][3]);
            pa[2] = packh2(accS[2 * s + 1][0], accS[2 * s + 1][1]);
            pa[3] = packh2(accS[2 * s + 1][2], accS[2 * s + 1][3]);
            #pragma unroll
            for (int np = 0; np < 8; np++) {
                uint32_t vb[4];
                ldsm4t(vb, smV + s * 16 * 272 + v_off + np * 32);
                mma16(accO[2 * np],     pa, vb);
                mma16(accO[2 * np + 1], pa, vb + 2);
            }
        }
    }

    const int bi = bh >> 4, h = bh & 15;
    const float inv0 = 1.0f / l0, inv1 = 1.0f / l1;
    const int row0 = it * 128 + r0 + lg;
    #pragma unroll
    for (int nt = 0; nt < 16; nt++) {
        const int d = 8 * nt + 2 * lp;
        *(uint32_t*)&g_attnh[((size_t)bi * T_ + row0) * C_ + h * 128 + d] =
            packh2(accO[nt][0] * inv0, accO[nt][1] * inv0);
        *(uint32_t*)&g_attnh[((size_t)bi * T_ + row0 + 8) * C_ + h * 128 + d] =
            packh2(accO[nt][2] * inv1, accO[nt][3] * inv1);
    }
}

// ---------------------------------------------------------------------------
// Launch
// ---------------------------------------------------------------------------
extern "C" void kernel_launch(void* const* d_in, const int* in_sizes, int n_in,
                              void* d_out, int out_size)
{
    const float* x = nullptr;
    const float* W_qkv = nullptr;
    const float* b_qkv = nullptr;
    const float* W_out = nullptr;
    const float* b_out = nullptr;
    int n4m_seen = 0;
    for (int i = 0; i < n_in; i++) {
        const int sz = in_sizes[i];
        if (sz == M_ * C_ && x == nullptr) x = (const float*)d_in[i];
        else if (sz == C_ * N1_) W_qkv = (const float*)d_in[i];
        else if (sz == N1_) b_qkv = (const float*)d_in[i];
        else if (sz == C_ * C_) {
            if (n4m_seen == 1) W_out = (const float*)d_in[i];
            n4m_seen++;
        }
        else if (sz == C_) b_out = (const float*)d_in[i];
    }
    float* out = (float*)d_out;

    // Device addresses of __device__ globals (must go through the runtime;
    // naming the symbol in host code yields a bogus host-side address).
    void *xh_p, *wqkvt_p, *woutt_p, *attnh_p, *gk_p, *gv_p;
    cudaGetSymbolAddress(&xh_p, g_xh);
    cudaGetSymbolAddress(&wqkvt_p, g_wqkvt);
    cudaGetSymbolAddress(&woutt_p, g_woutt);
    cudaGetSymbolAddress(&attnh_p, g_attnh);
    cudaGetSymbolAddress(&gk_p, g_k);
    cudaGetSymbolAddress(&gv_p, g_v);

    // k/v fp32 destinations: straight into d_out when it holds (out, k, v)
    float* kout = (out_size >= 3 * NKV) ? out + NKV : (float*)gk_p;
    float* vout = (out_size >= 3 * NKV) ? out + 2 * NKV : (float*)gv_p;

    cudaFuncSetAttribute(hgemm_kernel<0>,
                         cudaFuncAttributeMaxDynamicSharedMemorySize, GEMM_SMEM);
    cudaFuncSetAttribute(hgemm_kernel<1>,
                         cudaFuncAttributeMaxDynamicSharedMemorySize, GEMM_SMEM);
    cudaFuncSetAttribute(attn_tc_kernel,
                         cudaFuncAttributeMaxDynamicSharedMemorySize, ATTN_SMEM);

    // Fused prep (cvt x + transpose W_qkv + transpose W_out)
    prep_kernel<<<17408, 256>>>(x, W_qkv, W_out);

    // qkv: N=6144 -> 48 x 32 CTAs
    hgemm_kernel<0><<<dim3(48, 32), 128, GEMM_SMEM>>>(
        (const __half*)xh_p, (const __half*)wqkvt_p, b_qkv, nullptr,
        kout, vout);
    // attention: 16 q-tiles x 32 (b,h)
    attn_tc_kernel<<<dim3(16, 32), 256, ATTN_SMEM>>>();
    // out proj: N=2048 -> 16 x 32 CTAs
    hgemm_kernel<1><<<dim3(16, 32), 128, GEMM_SMEM>>>(
        (const __half*)attnh_p, (const __half*)woutt_p, b_out, out,
        nullptr, nullptr);
}